// round 13
// baseline (speedup 1.0000x reference)
#include <cuda_runtime.h>
#include <cuda_bf16.h>
#include <cstdint>

// ---------------- problem constants ----------------
#define CC      64
#define HH      120
#define WW      120
#define NBOX    8192
#define HID     128
#define SCOORD  (119.0f / 960.0f)

#define FIN_A   576
#define FIN_B   3136
#define FIN_C   7744

// k16-tiles per head: A 36, B 196, C 484 -> 716; group = 1 position = 4 tiles
#define T_A0    0
#define T_B0    36
#define T_C0    232
#define NTILES  716
#define N_ITEMS 896         // c: 4 chunks x 128 box-tiles, b: 2 x 128, a: 1 x 128
#define NSLAB   7           // c: 0-3, b: 4-5, a: 6

// smem layout (dynamic): boxp 1024 | A bufs 2 x 20800
#define ASUB    5200        // padded k16 sub-tile stride (64 rows x 80B + 80)
#define ABUF    20800       // 4 sub-tiles (one position)
#define SM_A    1024
#define SM_TOT  (SM_A + 2 * ABUF)      // 42624 -> 2 CTAs/SM fit

// ---------------- device scratch ----------------
__device__ float    d_fmT[HH * WW * CC];            // [y][x][c]
__device__ uint32_t d_Wp[NTILES * 2048];            // fragment-linear packed (hi,lo) B
__device__ float    d_Hpart[NSLAB * NBOX * HID];    // partial H slabs
__device__ float    d_gf[CC];
__device__ int      d_ctr;

// ---------------- helpers ----------------
__device__ __forceinline__ void ldsm4(uint32_t* r, uint32_t addr) {
    asm volatile("ldmatrix.sync.aligned.m8n8.x4.shared.b16 {%0,%1,%2,%3}, [%4];"
                 : "=r"(r[0]), "=r"(r[1]), "=r"(r[2]), "=r"(r[3]) : "r"(addr));
}
__device__ __forceinline__ void hmma(float* c, const uint32_t* a,
                                     uint32_t b0, uint32_t b1) {
    asm volatile("mma.sync.aligned.m16n8k16.row.col.f32.bf16.bf16.f32 "
                 "{%0,%1,%2,%3}, {%4,%5,%6,%7}, {%8,%9}, {%0,%1,%2,%3};"
                 : "+f"(c[0]), "+f"(c[1]), "+f"(c[2]), "+f"(c[3])
                 : "r"(a[0]), "r"(a[1]), "r"(a[2]), "r"(a[3]), "r"(b0), "r"(b1));
}
__device__ __forceinline__ uint32_t prmt(uint32_t a, uint32_t sel) {
    uint32_t d;
    asm("prmt.b32 %0, %1, %1, %2;" : "=r"(d) : "r"(a), "r"(sel));
    return d;
}
__device__ __forceinline__ uint32_t packhl(float x) {   // (lo<<16)|hi bf16 pair
    __nv_bfloat16 h = __float2bfloat16(x);
    __nv_bfloat16 l = __float2bfloat16(x - __bfloat162float(h));
    return ((uint32_t)__bfloat16_as_ushort(l) << 16) | (uint32_t)__bfloat16_as_ushort(h);
}
__device__ __forceinline__ uint32_t smem_u32(const void* p) {
    uint32_t a;
    asm("{ .reg .u64 t; cvta.to.shared.u64 t, %1; cvt.u32.u64 %0, t; }" : "=r"(a) : "l"(p));
    return a;
}

// ---------------- prep kernels ----------------
__global__ void transpose_fm_kernel(const float* __restrict__ fm) {
    int idx = blockIdx.x * 256 + threadIdx.x;
    if (idx == 0) d_ctr = 0;
    int c = idx & 63;
    int p = idx >> 6;
    d_fmT[idx] = fm[c * (HH * WW) + p];
}

// fragment-linear packed B, n16-granular (unchanged from R12)
__global__ void wp_prep_kernel(const float* __restrict__ W1a,
                               const float* __restrict__ W1b,
                               const float* __restrict__ W1c) {
    int idx = blockIdx.x * 256 + threadIdx.x;
    if (idx >= NTILES * 2048) return;
    int tg   = idx >> 11;
    int w    = idx & 2047;
    int nf2  = w & 1;
    int lane = (w >> 1) & 31;
    int b01  = (w >> 6) & 1;
    int s    = (w >> 7) & 1;
    int wn8  = (w >> 8) & 7;
    int k = s * 8 + b01 * 4 + (lane & 3);
    int n = wn8 * 16 + nf2 * 8 + (lane >> 2);
    const float* W; int fin, r2, tr;
    if (tg < T_B0)      { W = W1a; fin = FIN_A; r2 = 9;   tr = tg; }
    else if (tg < T_C0) { W = W1b; fin = FIN_B; r2 = 49;  tr = tg - T_B0; }
    else                { W = W1c; fin = FIN_C; r2 = 121; tr = tg - T_C0; }
    int kr  = tr * 16 + k;
    int pos = kr >> 6;
    int c   = kr & 63;
    d_Wp[idx] = packhl(W[n * fin + c * r2 + pos]);
}

__global__ void gf_kernel(const float* __restrict__ fm) {
    int c = blockIdx.x;
    float s = 0.0f;
    for (int i = threadIdx.x; i < HH * WW; i += 256) s += fm[c * (HH * WW) + i];
    __shared__ float red[8];
    #pragma unroll
    for (int off = 16; off; off >>= 1) s += __shfl_down_sync(0xffffffffu, s, off);
    if ((threadIdx.x & 31) == 0) red[threadIdx.x >> 5] = s;
    __syncthreads();
    if (threadIdx.x < 8) {
        s = red[threadIdx.x];
        #pragma unroll
        for (int off = 4; off; off >>= 1) s += __shfl_down_sync(0xffu, s, off);
        if (threadIdx.x == 0) d_gf[c] = s / (float)(HH * WW);
    }
}

// ---------------- persistent HMMA layer-1 kernel ----------------
// CTA tile 64 boxes x 128 hidden, 256 threads = 8 warps all in n (warp tile 64x16).
// 2 CTAs/SM. Scheduling: A-fragment ldsm pipelined one (st,s) unit ahead of the
// HMMAs; im2col for group g+1 split into issue(LDG)/commit(STS) phases pipelined
// one tile apart and interleaved into the MMA stream.

struct Pass {
    float4 t00, t01, t10, t11;
    float  w00, w01, w10, w11;
    int    mb;
};

__global__ void __launch_bounds__(256, 2)
layer1_kernel(const float* __restrict__ boxes) {
    extern __shared__ char smem[];
    float* boxp = (float*)smem;
    const uint32_t sbase = smem_u32(smem);
    __shared__ int s_item;

    const int tid    = threadIdx.x;
    const int wid    = tid >> 5;       // 0..7 = n-sixteenth
    const int lane   = tid & 31;
    const uint32_t laneOff = (uint32_t)(((lane & 7) + ((lane >> 3) & 1) * 8) * 80
                                        + (lane >> 4) * 16);
    const int f4i    = lane & 15;      // im2col: float4 channel index
    const int boxSel = lane >> 4;      // im2col: which of the pass's 2 boxes

    while (true) {
        if (tid == 0) s_item = atomicAdd(&d_ctr, 1);
        __syncthreads();
        const int item = s_item;
        if (item >= N_ITEMS) break;

        // decode item -> (head, 64-box tile, position chunk)
        int bt, pos0, npos, slab, r, headT0;
        float invr;
        if (item < 512) {                 // head c: 4 chunks {31,30,30,30}
            int ci = item >> 7; bt = item & 127;
            const int cst[4] = {0, 31, 61, 91};
            pos0 = cst[ci]; npos = (ci == 0) ? 31 : 30; slab = ci;
            r = 11; invr = 0.1f; headT0 = T_C0;
        } else if (item < 768) {          // head b: 2 chunks {25,24}
            int rel = item - 512;
            int ci = rel >> 7; bt = rel & 127;
            pos0 = ci ? 25 : 0; npos = ci ? 24 : 25; slab = 4 + ci;
            r = 7; invr = 1.0f / 6.0f; headT0 = T_B0;
        } else {                          // head a: 9 positions
            bt = item - 768;
            pos0 = 0; npos = 9; slab = 6;
            r = 3; invr = 0.5f; headT0 = T_A0;
        }
        const int box0 = bt * 64;

        if (tid < 64) {
            float4 b4 = __ldg(reinterpret_cast<const float4*>(boxes) + (box0 + tid));
            float4 o;
            o.x = b4.x * SCOORD;
            o.y = (b4.z - b4.x) * SCOORD;
            o.z = b4.y * SCOORD;
            o.w = (b4.w - b4.y) * SCOORD;
            *reinterpret_cast<float4*>(&boxp[tid * 4]) = o;
        }
        __syncthreads();

        float acc[4][2][4];               // [mf][nf2][quad]
        #pragma unroll
        for (int i = 0; i < 4; i++)
            #pragma unroll
            for (int j = 0; j < 2; j++)
                #pragma unroll
                for (int q = 0; q < 4; q++) acc[i][j][q] = 0.0f;

        // ---- im2col split into issue (coords + 4 tap LDGs) / commit (combine+STS) ----
        auto issue_pass = [&](int gp, int p, Pass& pr) {
            const int pos = pos0 + gp;
            const int py  = pos / r;
            const int px  = pos - py * r;
            const float tx = px * invr;
            const float ty = py * invr;
            const int mb = p * 16 + (wid << 1) + boxSel;
            pr.mb = mb;
            float4 bpv = *reinterpret_cast<const float4*>(&boxp[mb * 4]);
            float ix = fmaf(bpv.y, tx, bpv.x);
            float iy = fmaf(bpv.w, ty, bpv.z);
            float x0f = floorf(ix), y0f = floorf(iy);
            float wx = ix - x0f, wy = iy - y0f;
            int x0 = (int)x0f, y0 = (int)y0f;
            int x1 = x0 + 1,   y1 = y0 + 1;
            float vx0 = (x0 >= 0 && x0 < WW) ? 1.0f : 0.0f;
            float vx1 = (x1 >= 0 && x1 < WW) ? 1.0f : 0.0f;
            float vy0 = (y0 >= 0 && y0 < HH) ? 1.0f : 0.0f;
            float vy1 = (y1 >= 0 && y1 < HH) ? 1.0f : 0.0f;
            pr.w00 = (1.0f - wx) * (1.0f - wy) * vx0 * vy0;
            pr.w01 = wx * (1.0f - wy) * vx1 * vy0;
            pr.w10 = (1.0f - wx) * wy * vx0 * vy1;
            pr.w11 = wx * wy * vx1 * vy1;
            int cx0 = min(max(x0, 0), WW - 1), cx1 = min(max(x1, 0), WW - 1);
            int cy0 = min(max(y0, 0), HH - 1), cy1 = min(max(y1, 0), HH - 1);
            const float4* f = reinterpret_cast<const float4*>(d_fmT);
            pr.t00 = __ldg(&f[(cy0 * WW + cx0) * 16 + f4i]);
            pr.t01 = __ldg(&f[(cy0 * WW + cx1) * 16 + f4i]);
            pr.t10 = __ldg(&f[(cy1 * WW + cx0) * 16 + f4i]);
            pr.t11 = __ldg(&f[(cy1 * WW + cx1) * 16 + f4i]);
        };
        auto commit_pass = [&](int buf, const Pass& pr) {
            char* aB = smem + SM_A + buf * ABUF + (f4i >> 2) * ASUB + (f4i & 3) * 16;
            float4 v;
            v.x = pr.w00 * pr.t00.x + pr.w01 * pr.t01.x + pr.w10 * pr.t10.x + pr.w11 * pr.t11.x;
            v.y = pr.w00 * pr.t00.y + pr.w01 * pr.t01.y + pr.w10 * pr.t10.y + pr.w11 * pr.t11.y;
            v.z = pr.w00 * pr.t00.z + pr.w01 * pr.t01.z + pr.w10 * pr.t10.z + pr.w11 * pr.t11.z;
            v.w = pr.w00 * pr.t00.w + pr.w01 * pr.t01.w + pr.w10 * pr.t10.w + pr.w11 * pr.t11.w;
            uint4 wv;
            wv.x = packhl(v.x); wv.y = packhl(v.y);
            wv.z = packhl(v.z); wv.w = packhl(v.w);
            *reinterpret_cast<uint4*>(aB + pr.mb * 80) = wv;
        };

        // B fragments: 4 x uint2 per tile (s, b01)
        const char* wpB = (const char*)d_Wp + (size_t)wid * 1024 + (size_t)lane * 8;
        auto loadB = [&](int gt, uint2* q) {
            const char* src = wpB + (size_t)gt * 8192;
            q[0] = *reinterpret_cast<const uint2*>(src);
            q[1] = *reinterpret_cast<const uint2*>(src + 256);
            q[2] = *reinterpret_cast<const uint2*>(src + 512);
            q[3] = *reinterpret_cast<const uint2*>(src + 768);
        };

        const int gt0   = headT0 + pos0 * 4;
        const int gtEnd = gt0 + npos * 4;

        // prologue: A(0) (software-pipelined passes), B(gt0)
        {
            Pass p0, p1;
            issue_pass(0, 0, p0);
            #pragma unroll
            for (int p = 0; p < 4; ++p) {
                if (p < 3) issue_pass(0, p + 1, p1);
                commit_pass(0, p0);
                p0 = p1;
            }
        }
        uint2 bq[4], bqn[4];
        loadB(gt0, bq);
        __syncthreads();          // A(0) visible

        int gt = gt0;
        for (int gp = 0; gp < npos; ++gp) {
            const int buf = gp & 1;
            const bool haveNext = (gp + 1 < npos);
            const uint32_t aG = sbase + SM_A + buf * ABUF;

            uint32_t af[2][4][4];
            // unit 0 = (st0, s0)
            #pragma unroll
            for (int mf = 0; mf < 4; mf++)
                ldsm4(af[0][mf], aG + mf * 1280 + laneOff);

            Pass pr;
            int cur = 0;
            #pragma unroll
            for (int u = 0; u < 8; ++u) {
                const int st = u >> 1;
                const int s  = u & 1;

                if (s == 0 && gt + 1 < gtEnd) loadB(gt + 1, bqn);

                if (u < 7) {
                    const int un = u + 1;
                    const uint32_t aB = aG + (un >> 1) * ASUB + (un & 1) * 32 + laneOff;
                    #pragma unroll
                    for (int mf = 0; mf < 4; mf++)
                        ldsm4(af[cur ^ 1][mf], aB + mf * 1280);
                }

                // 16 HMMAs for this (st, s)
                {
                    const uint32_t* q0 = reinterpret_cast<const uint32_t*>(&bq[s * 2]);
                    const uint32_t* q1 = reinterpret_cast<const uint32_t*>(&bq[s * 2 + 1]);
                    #pragma unroll
                    for (int nf = 0; nf < 2; nf++) {
                        uint32_t b0h = prmt(q0[nf], 0x1010u);
                        uint32_t b1h = prmt(q1[nf], 0x1010u);
                        uint32_t b0l = prmt(q0[nf], 0x3232u);
                        uint32_t b1l = prmt(q1[nf], 0x3232u);
                        #pragma unroll
                        for (int mf = 0; mf < 4; mf++) {
                            hmma(acc[mf][nf], af[cur][mf], b0h, b1h);
                            hmma(acc[mf][nf], af[cur][mf], b0l, b1l);
                        }
                    }
                }

                if (s == 1) {   // tile boundary
                    if (haveNext) {
                        if (st > 0) commit_pass(buf ^ 1, pr);   // pass st-1 lands
                        issue_pass(gp + 1, st, pr);             // pass st LDGs fly
                    }
                    if (gt + 1 < gtEnd) {
                        bq[0] = bqn[0]; bq[1] = bqn[1];
                        bq[2] = bqn[2]; bq[3] = bqn[3];
                    }
                    ++gt;
                }
                cur ^= 1;
            }

            if (haveNext) {
                commit_pass(buf ^ 1, pr);   // final pass (st=3) of group gp+1
                __syncthreads();            // A(gp+1) visible to all warps
            }
        }

        // epilogue: write partial sums to slab
        {
            float* slabp = d_Hpart + (size_t)slab * (NBOX * HID) + (size_t)box0 * HID;
            const int rb = lane >> 2;
            const int cb = wid * 16 + (lane & 3) * 2;
            #pragma unroll
            for (int mf = 0; mf < 4; mf++) {
                #pragma unroll
                for (int nf = 0; nf < 2; nf++) {
                    int rr = rb + mf * 16;
                    int cc = cb + nf * 8;
                    *reinterpret_cast<float2*>(&slabp[rr * HID + cc]) =
                        make_float2(acc[mf][nf][0], acc[mf][nf][1]);
                    *reinterpret_cast<float2*>(&slabp[(rr + 8) * HID + cc]) =
                        make_float2(acc[mf][nf][2], acc[mf][nf][3]);
                }
            }
        }
        __syncthreads();   // boxp/s_item/bufs safe for next item
    }
}

// ---------------- finisher: slabs -> H -> layer-2; global head inline ----------------
__global__ void __launch_bounds__(256, 2)
finisher_kernel(const float* __restrict__ b1a, const float* __restrict__ W2a,
                const float* __restrict__ b2a,
                const float* __restrict__ b1b, const float* __restrict__ W2b,
                const float* __restrict__ b2b,
                const float* __restrict__ b1c, const float* __restrict__ W2c,
                const float* __restrict__ b2c,
                const float* __restrict__ scale_w,
                const float* __restrict__ Wg, const float* __restrict__ bg,
                float* __restrict__ out) {
    __shared__ float Hs[8192];
    __shared__ float sG[16];
    const int tid  = threadIdx.x;
    const int box0 = blockIdx.x * 64;

    if (tid < 16) {
        float s = bg[tid];
        #pragma unroll 8
        for (int c = 0; c < CC; c++) s += d_gf[c] * Wg[tid * CC + c];
        sG[tid] = s;
    }
    __syncthreads();
    for (int idx = tid; idx < 1024; idx += 256) {
        int mm = idx >> 4;
        int j  = idx & 15;
        out[(size_t)(box0 + mm) * 64 + 48 + j] = sG[j];
    }

    #pragma unroll
    for (int h = 0; h < 3; h++) {
        const float *b1, *W2, *b2;
        int slab0, nslab, od, col0, swi;
        if (h == 0)      { b1 = b1a; W2 = W2a; b2 = b2a; slab0 = 6; nslab = 1; od = 22; col0 = 0;  swi = 0; }
        else if (h == 1) { b1 = b1b; W2 = W2b; b2 = b2b; slab0 = 4; nslab = 2; od = 21; col0 = 22; swi = 1; }
        else             { b1 = b1c; W2 = W2c; b2 = b2c; slab0 = 0; nslab = 4; od = 5;  col0 = 43; swi = 2; }

        const size_t gbase = (size_t)box0 * HID;
        for (int i = tid * 4; i < 8192; i += 1024) {
            float4 s = *reinterpret_cast<const float4*>(
                &d_Hpart[(size_t)slab0 * (NBOX * HID) + gbase + i]);
            for (int q = 1; q < nslab; q++) {
                float4 t = *reinterpret_cast<const float4*>(
                    &d_Hpart[(size_t)(slab0 + q) * (NBOX * HID) + gbase + i]);
                s.x += t.x; s.y += t.y; s.z += t.z; s.w += t.w;
            }
            int n = i & 127;
            float4 bb = *reinterpret_cast<const float4*>(&b1[n]);
            s.x = fmaxf(s.x + bb.x, 0.0f);
            s.y = fmaxf(s.y + bb.y, 0.0f);
            s.z = fmaxf(s.z + bb.z, 0.0f);
            s.w = fmaxf(s.w + bb.w, 0.0f);
            *reinterpret_cast<float4*>(&Hs[i]) = s;
        }
        __syncthreads();

        const float sw = __ldg(&scale_w[swi]);
        const int njobs = od << 6;
        for (int job = tid; job < njobs; job += 256) {
            int mm = job / od;
            int o  = job - mm * od;
            float s = __ldg(&b2[o]);
            const float4* hrow = reinterpret_cast<const float4*>(&Hs[mm * 128]);
            const float4* wrow = reinterpret_cast<const float4*>(&W2[o * 128]);
            #pragma unroll 8
            for (int qq = 0; qq < 32; qq++) {
                float4 h4 = hrow[qq];
                float4 w4 = __ldg(&wrow[qq]);
                s += h4.x * w4.x + h4.y * w4.y + h4.z * w4.z + h4.w * w4.w;
            }
            out[(size_t)(box0 + mm) * 64 + col0 + o] = fmaxf(s, 0.0f) * sw;
        }
        __syncthreads();
    }
}

// ---------------- launch ----------------
extern "C" void kernel_launch(void* const* d_in, const int* in_sizes, int n_in,
                              void* d_out, int out_size) {
    const float* fm      = (const float*)d_in[0];
    const float* boxes   = (const float*)d_in[1];
    const float* W1a     = (const float*)d_in[2];
    const float* b1a     = (const float*)d_in[3];
    const float* W2a     = (const float*)d_in[4];
    const float* b2a     = (const float*)d_in[5];
    const float* W1b     = (const float*)d_in[6];
    const float* b1b     = (const float*)d_in[7];
    const float* W2b     = (const float*)d_in[8];
    const float* b2b     = (const float*)d_in[9];
    const float* W1c     = (const float*)d_in[10];
    const float* b1c     = (const float*)d_in[11];
    const float* W2c     = (const float*)d_in[12];
    const float* b2c     = (const float*)d_in[13];
    const float* scale_w = (const float*)d_in[14];
    const float* Wg      = (const float*)d_in[15];
    const float* bg      = (const float*)d_in[16];
    float* out = (float*)d_out;

    cudaFuncSetAttribute(layer1_kernel,
                         cudaFuncAttributeMaxDynamicSharedMemorySize, SM_TOT);

    transpose_fm_kernel<<<(HH * WW * CC) / 256, 256>>>(fm);
    wp_prep_kernel<<<(NTILES * 2048 + 255) / 256, 256>>>(W1a, W1b, W1c);
    gf_kernel<<<CC, 256>>>(fm);

    layer1_kernel<<<296, 256, SM_TOT>>>(boxes);

    finisher_kernel<<<NBOX / 64, 256>>>(b1a, W2a, b2a,
                                        b1b, W2b, b2b,
                                        b1c, W2c, b2c,
                                        scale_w, Wg, bg, out);
}

// round 14
// speedup vs baseline: 1.0668x; 1.0668x over previous
#include <cuda_runtime.h>
#include <cuda_bf16.h>
#include <cstdint>

// ---------------- problem constants ----------------
#define CC      64
#define HH      120
#define WW      120
#define NBOX    8192
#define HID     128
#define SCOORD  (119.0f / 960.0f)

#define FIN_A   576
#define FIN_B   3136
#define FIN_C   7744

// k16-tiles per head: A 36, B 196, C 484 -> 716; group = 1 position = 4 tiles
#define T_A0    0
#define T_B0    36
#define T_C0    232
#define NTILES  716
#define N_ITEMS 896         // c: 4 chunks x 128 box-tiles, b: 2 x 128, a: 1 x 128
#define NSLAB   7           // c: 0-3, b: 4-5, a: 6

// smem layout (dynamic): boxp 1024 | A bufs 2 x 20800
#define ASUB    5200        // padded k16 sub-tile stride (64 rows x 80B + 80)
#define ABUF    20800       // 4 sub-tiles (one position)
#define SM_A    1024
#define SM_TOT  (SM_A + 2 * ABUF)      // 42624 -> 2 CTAs/SM fit

// ---------------- device scratch ----------------
__device__ float    d_fmT[HH * WW * CC];            // [y][x][c]
__device__ uint32_t d_Wp[NTILES * 2048];            // fragment-linear packed (hi,lo) B
__device__ float    d_Hpart[NSLAB * NBOX * HID];    // partial H slabs
__device__ float    d_gf[CC];
__device__ int      d_ctr;

// ---------------- helpers ----------------
__device__ __forceinline__ void ldsm4(uint32_t* r, uint32_t addr) {
    asm volatile("ldmatrix.sync.aligned.m8n8.x4.shared.b16 {%0,%1,%2,%3}, [%4];"
                 : "=r"(r[0]), "=r"(r[1]), "=r"(r[2]), "=r"(r[3]) : "r"(addr));
}
__device__ __forceinline__ void hmma(float* c, const uint32_t* a,
                                     uint32_t b0, uint32_t b1) {
    asm volatile("mma.sync.aligned.m16n8k16.row.col.f32.bf16.bf16.f32 "
                 "{%0,%1,%2,%3}, {%4,%5,%6,%7}, {%8,%9}, {%0,%1,%2,%3};"
                 : "+f"(c[0]), "+f"(c[1]), "+f"(c[2]), "+f"(c[3])
                 : "r"(a[0]), "r"(a[1]), "r"(a[2]), "r"(a[3]), "r"(b0), "r"(b1));
}
__device__ __forceinline__ uint32_t prmt(uint32_t a, uint32_t sel) {
    uint32_t d;
    asm("prmt.b32 %0, %1, %1, %2;" : "=r"(d) : "r"(a), "r"(sel));
    return d;
}
__device__ __forceinline__ uint32_t packhl(float x) {   // (lo<<16)|hi bf16 pair
    __nv_bfloat16 h = __float2bfloat16(x);
    __nv_bfloat16 l = __float2bfloat16(x - __bfloat162float(h));
    return ((uint32_t)__bfloat16_as_ushort(l) << 16) | (uint32_t)__bfloat16_as_ushort(h);
}
__device__ __forceinline__ uint32_t smem_u32(const void* p) {
    uint32_t a;
    asm("{ .reg .u64 t; cvta.to.shared.u64 t, %1; cvt.u32.u64 %0, t; }" : "=r"(a) : "l"(p));
    return a;
}

// ---------------- prep kernels ----------------
__global__ void transpose_fm_kernel(const float* __restrict__ fm) {
    int idx = blockIdx.x * 256 + threadIdx.x;
    if (idx == 0) d_ctr = 0;
    int c = idx & 63;
    int p = idx >> 6;
    d_fmT[idx] = fm[c * (HH * WW) + p];
}

// fragment-linear packed B, n16-granular (unchanged from R12)
__global__ void wp_prep_kernel(const float* __restrict__ W1a,
                               const float* __restrict__ W1b,
                               const float* __restrict__ W1c) {
    int idx = blockIdx.x * 256 + threadIdx.x;
    if (idx >= NTILES * 2048) return;
    int tg   = idx >> 11;
    int w    = idx & 2047;
    int nf2  = w & 1;
    int lane = (w >> 1) & 31;
    int b01  = (w >> 6) & 1;
    int s    = (w >> 7) & 1;
    int wn8  = (w >> 8) & 7;
    int k = s * 8 + b01 * 4 + (lane & 3);
    int n = wn8 * 16 + nf2 * 8 + (lane >> 2);
    const float* W; int fin, r2, tr;
    if (tg < T_B0)      { W = W1a; fin = FIN_A; r2 = 9;   tr = tg; }
    else if (tg < T_C0) { W = W1b; fin = FIN_B; r2 = 49;  tr = tg - T_B0; }
    else                { W = W1c; fin = FIN_C; r2 = 121; tr = tg - T_C0; }
    int kr  = tr * 16 + k;
    int pos = kr >> 6;
    int c   = kr & 63;
    d_Wp[idx] = packhl(W[n * fin + c * r2 + pos]);
}

__global__ void gf_kernel(const float* __restrict__ fm) {
    int c = blockIdx.x;
    float s = 0.0f;
    for (int i = threadIdx.x; i < HH * WW; i += 256) s += fm[c * (HH * WW) + i];
    __shared__ float red[8];
    #pragma unroll
    for (int off = 16; off; off >>= 1) s += __shfl_down_sync(0xffffffffu, s, off);
    if ((threadIdx.x & 31) == 0) red[threadIdx.x >> 5] = s;
    __syncthreads();
    if (threadIdx.x < 8) {
        s = red[threadIdx.x];
        #pragma unroll
        for (int off = 4; off; off >>= 1) s += __shfl_down_sync(0xffu, s, off);
        if (threadIdx.x == 0) d_gf[c] = s / (float)(HH * WW);
    }
}

// ---------------- persistent HMMA layer-1 kernel ----------------
// CTA tile 64 boxes x 128 hidden, 256 threads = 8 warps all in n (warp tile 64x16).
// 2 CTAs/SM. Inner unit reordered: 8 independent hi-HMMAs, then 8 lo-HMMAs, so
// the hi->lo accumulator RAW pair is separated by >= 11 instructions.

__global__ void __launch_bounds__(256, 2)
layer1_kernel(const float* __restrict__ boxes) {
    extern __shared__ char smem[];
    float* boxp = (float*)smem;
    const uint32_t sbase = smem_u32(smem);
    __shared__ int s_item;

    const int tid    = threadIdx.x;
    const int wid    = tid >> 5;       // 0..7 = n-sixteenth
    const int lane   = tid & 31;
    const uint32_t laneOff = (uint32_t)(((lane & 7) + ((lane >> 3) & 1) * 8) * 80
                                        + (lane >> 4) * 16);
    const int f4i    = lane & 15;      // im2col: float4 channel index
    const int boxSel = lane >> 4;      // im2col: which of the pass's 2 boxes

    while (true) {
        if (tid == 0) s_item = atomicAdd(&d_ctr, 1);
        __syncthreads();
        const int item = s_item;
        if (item >= N_ITEMS) break;

        // decode item -> (head, 64-box tile, position chunk)
        int bt, pos0, npos, slab, r, headT0;
        float invr;
        if (item < 512) {                 // head c: 4 chunks {31,30,30,30}
            int ci = item >> 7; bt = item & 127;
            const int cst[4] = {0, 31, 61, 91};
            pos0 = cst[ci]; npos = (ci == 0) ? 31 : 30; slab = ci;
            r = 11; invr = 0.1f; headT0 = T_C0;
        } else if (item < 768) {          // head b: 2 chunks {25,24}
            int rel = item - 512;
            int ci = rel >> 7; bt = rel & 127;
            pos0 = ci ? 25 : 0; npos = ci ? 24 : 25; slab = 4 + ci;
            r = 7; invr = 1.0f / 6.0f; headT0 = T_B0;
        } else {                          // head a: 9 positions
            bt = item - 768;
            pos0 = 0; npos = 9; slab = 6;
            r = 3; invr = 0.5f; headT0 = T_A0;
        }
        const int box0 = bt * 64;

        if (tid < 64) {
            float4 b4 = __ldg(reinterpret_cast<const float4*>(boxes) + (box0 + tid));
            float4 o;
            o.x = b4.x * SCOORD;
            o.y = (b4.z - b4.x) * SCOORD;
            o.z = b4.y * SCOORD;
            o.w = (b4.w - b4.y) * SCOORD;
            *reinterpret_cast<float4*>(&boxp[tid * 4]) = o;
        }
        __syncthreads();

        float acc[4][2][4];               // [mf][nf2][quad]
        #pragma unroll
        for (int i = 0; i < 4; i++)
            #pragma unroll
            for (int j = 0; j < 2; j++)
                #pragma unroll
                for (int q = 0; q < 4; q++) acc[i][j][q] = 0.0f;

        // ---- coalesced im2col: one position group (64 boxes, 4 passes) ----
        auto do_im2col = [&](int gp, int buf) {
            const int pos = pos0 + gp;
            const int py  = pos / r;
            const int px  = pos - py * r;
            const float tx = px * invr;
            const float ty = py * invr;
            char* aB = smem + SM_A + buf * ABUF + (f4i >> 2) * ASUB + (f4i & 3) * 16;
            const float4* f = reinterpret_cast<const float4*>(d_fmT);
            #pragma unroll
            for (int p = 0; p < 4; ++p) {
                const int mb = p * 16 + (wid << 1) + boxSel;
                float4 bpv = *reinterpret_cast<const float4*>(&boxp[mb * 4]);
                float ix = fmaf(bpv.y, tx, bpv.x);
                float iy = fmaf(bpv.w, ty, bpv.z);
                float x0f = floorf(ix), y0f = floorf(iy);
                float wx = ix - x0f, wy = iy - y0f;
                int x0 = (int)x0f, y0 = (int)y0f;
                int x1 = x0 + 1,   y1 = y0 + 1;
                float vx0 = (x0 >= 0 && x0 < WW) ? 1.0f : 0.0f;
                float vx1 = (x1 >= 0 && x1 < WW) ? 1.0f : 0.0f;
                float vy0 = (y0 >= 0 && y0 < HH) ? 1.0f : 0.0f;
                float vy1 = (y1 >= 0 && y1 < HH) ? 1.0f : 0.0f;
                float w00 = (1.0f - wx) * (1.0f - wy) * vx0 * vy0;
                float w01 = wx * (1.0f - wy) * vx1 * vy0;
                float w10 = (1.0f - wx) * wy * vx0 * vy1;
                float w11 = wx * wy * vx1 * vy1;
                int cx0 = min(max(x0, 0), WW - 1), cx1 = min(max(x1, 0), WW - 1);
                int cy0 = min(max(y0, 0), HH - 1), cy1 = min(max(y1, 0), HH - 1);
                float4 t00 = __ldg(&f[(cy0 * WW + cx0) * 16 + f4i]);
                float4 t01 = __ldg(&f[(cy0 * WW + cx1) * 16 + f4i]);
                float4 t10 = __ldg(&f[(cy1 * WW + cx0) * 16 + f4i]);
                float4 t11 = __ldg(&f[(cy1 * WW + cx1) * 16 + f4i]);
                float4 v;
                v.x = w00 * t00.x + w01 * t01.x + w10 * t10.x + w11 * t11.x;
                v.y = w00 * t00.y + w01 * t01.y + w10 * t10.y + w11 * t11.y;
                v.z = w00 * t00.z + w01 * t01.z + w10 * t10.z + w11 * t11.z;
                v.w = w00 * t00.w + w01 * t01.w + w10 * t10.w + w11 * t11.w;
                uint4 wv;
                wv.x = packhl(v.x); wv.y = packhl(v.y);
                wv.z = packhl(v.z); wv.w = packhl(v.w);
                *reinterpret_cast<uint4*>(aB + mb * 80) = wv;
            }
        };

        // B fragments: 4 x uint2 per tile (s, b01), n16 slice for this warp
        const char* wpB = (const char*)d_Wp + (size_t)wid * 1024 + (size_t)lane * 8;
        auto loadB = [&](int gt, uint2* q) {
            const char* src = wpB + (size_t)gt * 8192;
            q[0] = *reinterpret_cast<const uint2*>(src);          // s0,b0
            q[1] = *reinterpret_cast<const uint2*>(src + 256);    // s0,b1
            q[2] = *reinterpret_cast<const uint2*>(src + 512);    // s1,b0
            q[3] = *reinterpret_cast<const uint2*>(src + 768);    // s1,b1
        };

        const int gt0   = headT0 + pos0 * 4;
        const int gtEnd = gt0 + npos * 4;

        do_im2col(0, 0);
        uint2 bq[4];
        loadB(gt0, bq);
        __syncthreads();          // A(0) visible

        int gt = gt0;
        for (int gp = 0; gp < npos; ++gp) {
            const int buf = gp & 1;
            const uint32_t aG = sbase + SM_A + buf * ABUF;

            #pragma unroll 4
            for (int st = 0; st < 4; ++st, ++gt) {
                uint2 bqn[4];
                if (gt + 1 < gtEnd) loadB(gt + 1, bqn);

                const uint32_t aB = aG + st * ASUB;
                #pragma unroll
                for (int s = 0; s < 2; s++) {
                    uint32_t af[4][4];
                    #pragma unroll
                    for (int mf = 0; mf < 4; mf++)
                        ldsm4(af[mf], aB + mf * 1280 + s * 32 + laneOff);
                    const uint32_t* q0 = reinterpret_cast<const uint32_t*>(&bq[s * 2]);
                    const uint32_t* q1 = reinterpret_cast<const uint32_t*>(&bq[s * 2 + 1]);

                    // hi batch: 8 independent HMMAs
                    uint32_t h00 = prmt(q0[0], 0x1010u);
                    uint32_t h10 = prmt(q1[0], 0x1010u);
                    uint32_t h01 = prmt(q0[1], 0x1010u);
                    uint32_t h11 = prmt(q1[1], 0x1010u);
                    #pragma unroll
                    for (int mf = 0; mf < 4; mf++) hmma(acc[mf][0], af[mf], h00, h10);
                    #pragma unroll
                    for (int mf = 0; mf < 4; mf++) hmma(acc[mf][1], af[mf], h01, h11);

                    // lo batch: dependent pair is >= 11 instructions behind
                    uint32_t l00 = prmt(q0[0], 0x3232u);
                    uint32_t l10 = prmt(q1[0], 0x3232u);
                    uint32_t l01 = prmt(q0[1], 0x3232u);
                    uint32_t l11 = prmt(q1[1], 0x3232u);
                    #pragma unroll
                    for (int mf = 0; mf < 4; mf++) hmma(acc[mf][0], af[mf], l00, l10);
                    #pragma unroll
                    for (int mf = 0; mf < 4; mf++) hmma(acc[mf][1], af[mf], l01, l11);
                }
                if (gt + 1 < gtEnd) {
                    bq[0] = bqn[0]; bq[1] = bqn[1];
                    bq[2] = bqn[2]; bq[3] = bqn[3];
                }
            }

            if (gp + 1 < npos) {
                do_im2col(gp + 1, buf ^ 1);
                __syncthreads();      // A(gp+1) visible to all warps
            }
        }

        // epilogue: write partial sums to slab
        {
            float* slabp = d_Hpart + (size_t)slab * (NBOX * HID) + (size_t)box0 * HID;
            const int rb = lane >> 2;
            const int cb = wid * 16 + (lane & 3) * 2;
            #pragma unroll
            for (int mf = 0; mf < 4; mf++) {
                #pragma unroll
                for (int nf = 0; nf < 2; nf++) {
                    int rr = rb + mf * 16;
                    int cc = cb + nf * 8;
                    *reinterpret_cast<float2*>(&slabp[rr * HID + cc]) =
                        make_float2(acc[mf][nf][0], acc[mf][nf][1]);
                    *reinterpret_cast<float2*>(&slabp[(rr + 8) * HID + cc]) =
                        make_float2(acc[mf][nf][2], acc[mf][nf][3]);
                }
            }
        }
        __syncthreads();   // boxp/s_item/bufs safe for next item
    }
}

// ---------------- finisher: slabs -> H -> layer-2; global head inline ----------------
__global__ void __launch_bounds__(256, 2)
finisher_kernel(const float* __restrict__ b1a, const float* __restrict__ W2a,
                const float* __restrict__ b2a,
                const float* __restrict__ b1b, const float* __restrict__ W2b,
                const float* __restrict__ b2b,
                const float* __restrict__ b1c, const float* __restrict__ W2c,
                const float* __restrict__ b2c,
                const float* __restrict__ scale_w,
                const float* __restrict__ Wg, const float* __restrict__ bg,
                float* __restrict__ out) {
    __shared__ float Hs[8192];
    __shared__ float sG[16];
    const int tid  = threadIdx.x;
    const int box0 = blockIdx.x * 64;

    if (tid < 16) {
        float s = bg[tid];
        #pragma unroll 8
        for (int c = 0; c < CC; c++) s += d_gf[c] * Wg[tid * CC + c];
        sG[tid] = s;
    }
    __syncthreads();
    for (int idx = tid; idx < 1024; idx += 256) {
        int mm = idx >> 4;
        int j  = idx & 15;
        out[(size_t)(box0 + mm) * 64 + 48 + j] = sG[j];
    }

    #pragma unroll
    for (int h = 0; h < 3; h++) {
        const float *b1, *W2, *b2;
        int slab0, nslab, od, col0, swi;
        if (h == 0)      { b1 = b1a; W2 = W2a; b2 = b2a; slab0 = 6; nslab = 1; od = 22; col0 = 0;  swi = 0; }
        else if (h == 1) { b1 = b1b; W2 = W2b; b2 = b2b; slab0 = 4; nslab = 2; od = 21; col0 = 22; swi = 1; }
        else             { b1 = b1c; W2 = W2c; b2 = b2c; slab0 = 0; nslab = 4; od = 5;  col0 = 43; swi = 2; }

        const size_t gbase = (size_t)box0 * HID;
        for (int i = tid * 4; i < 8192; i += 1024) {
            float4 s = *reinterpret_cast<const float4*>(
                &d_Hpart[(size_t)slab0 * (NBOX * HID) + gbase + i]);
            for (int q = 1; q < nslab; q++) {
                float4 t = *reinterpret_cast<const float4*>(
                    &d_Hpart[(size_t)(slab0 + q) * (NBOX * HID) + gbase + i]);
                s.x += t.x; s.y += t.y; s.z += t.z; s.w += t.w;
            }
            int n = i & 127;
            float4 bb = *reinterpret_cast<const float4*>(&b1[n]);
            s.x = fmaxf(s.x + bb.x, 0.0f);
            s.y = fmaxf(s.y + bb.y, 0.0f);
            s.z = fmaxf(s.z + bb.z, 0.0f);
            s.w = fmaxf(s.w + bb.w, 0.0f);
            *reinterpret_cast<float4*>(&Hs[i]) = s;
        }
        __syncthreads();

        const float sw = __ldg(&scale_w[swi]);
        const int njobs = od << 6;
        for (int job = tid; job < njobs; job += 256) {
            int mm = job / od;
            int o  = job - mm * od;
            float s = __ldg(&b2[o]);
            const float4* hrow = reinterpret_cast<const float4*>(&Hs[mm * 128]);
            const float4* wrow = reinterpret_cast<const float4*>(&W2[o * 128]);
            #pragma unroll 8
            for (int qq = 0; qq < 32; qq++) {
                float4 h4 = hrow[qq];
                float4 w4 = __ldg(&wrow[qq]);
                s += h4.x * w4.x + h4.y * w4.y + h4.z * w4.z + h4.w * w4.w;
            }
            out[(size_t)(box0 + mm) * 64 + col0 + o] = fmaxf(s, 0.0f) * sw;
        }
        __syncthreads();
    }
}

// ---------------- launch ----------------
extern "C" void kernel_launch(void* const* d_in, const int* in_sizes, int n_in,
                              void* d_out, int out_size) {
    const float* fm      = (const float*)d_in[0];
    const float* boxes   = (const float*)d_in[1];
    const float* W1a     = (const float*)d_in[2];
    const float* b1a     = (const float*)d_in[3];
    const float* W2a     = (const float*)d_in[4];
    const float* b2a     = (const float*)d_in[5];
    const float* W1b     = (const float*)d_in[6];
    const float* b1b     = (const float*)d_in[7];
    const float* W2b     = (const float*)d_in[8];
    const float* b2b     = (const float*)d_in[9];
    const float* W1c     = (const float*)d_in[10];
    const float* b1c     = (const float*)d_in[11];
    const float* W2c     = (const float*)d_in[12];
    const float* b2c     = (const float*)d_in[13];
    const float* scale_w = (const float*)d_in[14];
    const float* Wg      = (const float*)d_in[15];
    const float* bg      = (const float*)d_in[16];
    float* out = (float*)d_out;

    cudaFuncSetAttribute(layer1_kernel,
                         cudaFuncAttributeMaxDynamicSharedMemorySize, SM_TOT);

    transpose_fm_kernel<<<(HH * WW * CC) / 256, 256>>>(fm);
    wp_prep_kernel<<<(NTILES * 2048 + 255) / 256, 256>>>(W1a, W1b, W1c);
    gf_kernel<<<CC, 256>>>(fm);

    layer1_kernel<<<296, 256, SM_TOT>>>(boxes);

    finisher_kernel<<<NBOX / 64, 256>>>(b1a, W2a, b2a,
                                        b1b, W2b, b2b,
                                        b1c, W2c, b2c,
                                        scale_w, Wg, bg, out);
}

// round 15
// speedup vs baseline: 1.2452x; 1.1673x over previous
#include <cuda_runtime.h>
#include <cuda_fp16.h>
#include <cstdint>

// ---------------- problem constants ----------------
#define CC      64
#define HH      120
#define WW      120
#define NBOX    8192
#define HID     128
#define SCOORD  (119.0f / 960.0f)

#define FIN_A   576
#define FIN_B   3136
#define FIN_C   7744

// k16-tiles per head: A 36, B 196, C 484 -> 716; group = 1 position = 4 tiles
#define T_A0    0
#define T_B0    36
#define T_C0    232
#define NTILES  716
#define N_ITEMS 896         // c: 4 chunks x 128 box-tiles, b: 2 x 128, a: 1 x 128
#define NSLAB   7           // c: 0-3, b: 4-5, a: 6

// smem layout (dynamic): boxp 1024 | A bufs 2 x 20800
#define ASUB    5200        // padded k16 sub-tile stride (64 rows x 80B + 80)
#define ABUF    20800       // 4 sub-tiles (one position)
#define SM_A    1024
#define SM_TOT  (SM_A + 2 * ABUF)      // 42624 -> 2 CTAs/SM fit

// merged prep grid split
#define PREP_FM_BLKS  3600              // 921600 / 256
#define PREP_WP_BLKS  5728              // NTILES*2048 / 256
#define PREP_GF_BLKS  64
#define PREP_BLKS     (PREP_FM_BLKS + PREP_WP_BLKS + PREP_GF_BLKS)

// ---------------- device scratch ----------------
__device__ float    d_fmT[HH * WW * CC];            // [y][x][c]
__device__ uint32_t d_Wp[NTILES * 2048];            // fragment-linear dup fp16 B
__device__ float    d_Hpart[NSLAB * NBOX * HID];    // partial H slabs
__device__ float    d_gf[CC];
__device__ int      d_ctr;

// ---------------- helpers ----------------
__device__ __forceinline__ void ldsm4(uint32_t* r, uint32_t addr) {
    asm volatile("ldmatrix.sync.aligned.m8n8.x4.shared.b16 {%0,%1,%2,%3}, [%4];"
                 : "=r"(r[0]), "=r"(r[1]), "=r"(r[2]), "=r"(r[3]) : "r"(addr));
}
__device__ __forceinline__ void hmma16(float* c, const uint32_t* a,
                                       uint32_t b0, uint32_t b1) {
    asm volatile("mma.sync.aligned.m16n8k16.row.col.f32.f16.f16.f32 "
                 "{%0,%1,%2,%3}, {%4,%5,%6,%7}, {%8,%9}, {%0,%1,%2,%3};"
                 : "+f"(c[0]), "+f"(c[1]), "+f"(c[2]), "+f"(c[3])
                 : "r"(a[0]), "r"(a[1]), "r"(a[2]), "r"(a[3]), "r"(b0), "r"(b1));
}
__device__ __forceinline__ uint32_t packhl16(float x) {   // (lo<<16)|hi fp16 pair
    __half h = __float2half(x);
    __half l = __float2half(x - __half2float(h));
    return ((uint32_t)__half_as_ushort(l) << 16) | (uint32_t)__half_as_ushort(h);
}
__device__ __forceinline__ uint32_t smem_u32(const void* p) {
    uint32_t a;
    asm("{ .reg .u64 t; cvta.to.shared.u64 t, %1; cvt.u32.u64 %0, t; }" : "=r"(a) : "l"(p));
    return a;
}

// ---------------- merged prep kernel ----------------
// blocks [0, 3600): fm transpose; [3600, 9328): B fragment images; [9328, 9392): gf
__global__ void prep_all_kernel(const float* __restrict__ fm,
                                const float* __restrict__ W1a,
                                const float* __restrict__ W1b,
                                const float* __restrict__ W1c) {
    __shared__ float red[8];
    const int b = blockIdx.x;
    if (b < PREP_FM_BLKS) {
        int idx = b * 256 + threadIdx.x;
        if (idx == 0) d_ctr = 0;
        int c = idx & 63;
        int p = idx >> 6;
        d_fmT[idx] = fm[c * (HH * WW) + p];
    } else if (b < PREP_FM_BLKS + PREP_WP_BLKS) {
        int idx = (b - PREP_FM_BLKS) * 256 + threadIdx.x;
        // word (tg, wn8, s, b01, lane, nf2): k = s*8+b01*4+(lane&3),
        // n = wn8*16+nf2*8+(lane>>2); content = dup fp16(b)
        int tg   = idx >> 11;
        int w    = idx & 2047;
        int nf2  = w & 1;
        int lane = (w >> 1) & 31;
        int b01  = (w >> 6) & 1;
        int s    = (w >> 7) & 1;
        int wn8  = (w >> 8) & 7;
        int k = s * 8 + b01 * 4 + (lane & 3);
        int n = wn8 * 16 + nf2 * 8 + (lane >> 2);
        const float* W; int fin, r2, tr;
        if (tg < T_B0)      { W = W1a; fin = FIN_A; r2 = 9;   tr = tg; }
        else if (tg < T_C0) { W = W1b; fin = FIN_B; r2 = 49;  tr = tg - T_B0; }
        else                { W = W1c; fin = FIN_C; r2 = 121; tr = tg - T_C0; }
        int kr  = tr * 16 + k;
        int pos = kr >> 6;
        int c   = kr & 63;
        uint32_t hb = (uint32_t)__half_as_ushort(__float2half(W[n * fin + c * r2 + pos]));
        d_Wp[idx] = (hb << 16) | hb;
    } else {
        int c = b - (PREP_FM_BLKS + PREP_WP_BLKS);
        float s = 0.0f;
        for (int i = threadIdx.x; i < HH * WW; i += 256) s += fm[c * (HH * WW) + i];
        #pragma unroll
        for (int off = 16; off; off >>= 1) s += __shfl_down_sync(0xffffffffu, s, off);
        if ((threadIdx.x & 31) == 0) red[threadIdx.x >> 5] = s;
        __syncthreads();
        if (threadIdx.x < 8) {
            s = red[threadIdx.x];
            #pragma unroll
            for (int off = 4; off; off >>= 1) s += __shfl_down_sync(0xffu, s, off);
            if (threadIdx.x == 0) d_gf[c] = s / (float)(HH * WW);
        }
    }
}

// ---------------- persistent HMMA layer-1 kernel ----------------
// CTA tile 64 boxes x 128 hidden, 256 threads = 8 warps all in n (warp tile 64x16).
// 2 CTAs/SM. fp16 split: A k'-interleaved (hi,lo); ONE dup-fp16 B image ->
// half the HMMAs of the bf16 scheme, zero PRMT.

__global__ void __launch_bounds__(256, 2)
layer1_kernel(const float* __restrict__ boxes) {
    extern __shared__ char smem[];
    float* boxp = (float*)smem;
    const uint32_t sbase = smem_u32(smem);
    __shared__ int s_item;

    const int tid    = threadIdx.x;
    const int wid    = tid >> 5;       // 0..7 = n-sixteenth
    const int lane   = tid & 31;
    const uint32_t laneOff = (uint32_t)(((lane & 7) + ((lane >> 3) & 1) * 8) * 80
                                        + (lane >> 4) * 16);
    const int f4i    = lane & 15;      // im2col: float4 channel index
    const int boxSel = lane >> 4;      // im2col: which of the pass's 2 boxes

    while (true) {
        if (tid == 0) s_item = atomicAdd(&d_ctr, 1);
        __syncthreads();
        const int item = s_item;
        if (item >= N_ITEMS) break;

        // decode item -> (head, 64-box tile, position chunk)
        int bt, pos0, npos, slab, r, headT0;
        float invr;
        if (item < 512) {                 // head c: 4 chunks {31,30,30,30}
            int ci = item >> 7; bt = item & 127;
            const int cst[4] = {0, 31, 61, 91};
            pos0 = cst[ci]; npos = (ci == 0) ? 31 : 30; slab = ci;
            r = 11; invr = 0.1f; headT0 = T_C0;
        } else if (item < 768) {          // head b: 2 chunks {25,24}
            int rel = item - 512;
            int ci = rel >> 7; bt = rel & 127;
            pos0 = ci ? 25 : 0; npos = ci ? 24 : 25; slab = 4 + ci;
            r = 7; invr = 1.0f / 6.0f; headT0 = T_B0;
        } else {                          // head a: 9 positions
            bt = item - 768;
            pos0 = 0; npos = 9; slab = 6;
            r = 3; invr = 0.5f; headT0 = T_A0;
        }
        const int box0 = bt * 64;

        if (tid < 64) {
            float4 b4 = __ldg(reinterpret_cast<const float4*>(boxes) + (box0 + tid));
            float4 o;
            o.x = b4.x * SCOORD;
            o.y = (b4.z - b4.x) * SCOORD;
            o.z = b4.y * SCOORD;
            o.w = (b4.w - b4.y) * SCOORD;
            *reinterpret_cast<float4*>(&boxp[tid * 4]) = o;
        }
        __syncthreads();

        float acc[4][2][4];               // [mf][nf2][quad]
        #pragma unroll
        for (int i = 0; i < 4; i++)
            #pragma unroll
            for (int j = 0; j < 2; j++)
                #pragma unroll
                for (int q = 0; q < 4; q++) acc[i][j][q] = 0.0f;

        // ---- coalesced im2col: one position group (64 boxes, 4 passes) ----
        auto do_im2col = [&](int gp, int buf) {
            const int pos = pos0 + gp;
            const int py  = pos / r;
            const int px  = pos - py * r;
            const float tx = px * invr;
            const float ty = py * invr;
            char* aB = smem + SM_A + buf * ABUF + (f4i >> 2) * ASUB + (f4i & 3) * 16;
            const float4* f = reinterpret_cast<const float4*>(d_fmT);
            #pragma unroll
            for (int p = 0; p < 4; ++p) {
                const int mb = p * 16 + (wid << 1) + boxSel;
                float4 bpv = *reinterpret_cast<const float4*>(&boxp[mb * 4]);
                float ix = fmaf(bpv.y, tx, bpv.x);
                float iy = fmaf(bpv.w, ty, bpv.z);
                float x0f = floorf(ix), y0f = floorf(iy);
                float wx = ix - x0f, wy = iy - y0f;
                int x0 = (int)x0f, y0 = (int)y0f;
                int x1 = x0 + 1,   y1 = y0 + 1;
                float vx0 = (x0 >= 0 && x0 < WW) ? 1.0f : 0.0f;
                float vx1 = (x1 >= 0 && x1 < WW) ? 1.0f : 0.0f;
                float vy0 = (y0 >= 0 && y0 < HH) ? 1.0f : 0.0f;
                float vy1 = (y1 >= 0 && y1 < HH) ? 1.0f : 0.0f;
                float w00 = (1.0f - wx) * (1.0f - wy) * vx0 * vy0;
                float w01 = wx * (1.0f - wy) * vx1 * vy0;
                float w10 = (1.0f - wx) * wy * vx0 * vy1;
                float w11 = wx * wy * vx1 * vy1;
                int cx0 = min(max(x0, 0), WW - 1), cx1 = min(max(x1, 0), WW - 1);
                int cy0 = min(max(y0, 0), HH - 1), cy1 = min(max(y1, 0), HH - 1);
                float4 t00 = __ldg(&f[(cy0 * WW + cx0) * 16 + f4i]);
                float4 t01 = __ldg(&f[(cy0 * WW + cx1) * 16 + f4i]);
                float4 t10 = __ldg(&f[(cy1 * WW + cx0) * 16 + f4i]);
                float4 t11 = __ldg(&f[(cy1 * WW + cx1) * 16 + f4i]);
                float4 v;
                v.x = w00 * t00.x + w01 * t01.x + w10 * t10.x + w11 * t11.x;
                v.y = w00 * t00.y + w01 * t01.y + w10 * t10.y + w11 * t11.y;
                v.z = w00 * t00.z + w01 * t01.z + w10 * t10.z + w11 * t11.z;
                v.w = w00 * t00.w + w01 * t01.w + w10 * t10.w + w11 * t11.w;
                uint4 wv;
                wv.x = packhl16(v.x); wv.y = packhl16(v.y);
                wv.z = packhl16(v.z); wv.w = packhl16(v.w);
                *reinterpret_cast<uint4*>(aB + mb * 80) = wv;
            }
        };

        // B fragments: 4 x uint2 per tile (s, b01), n16 slice for this warp
        const char* wpB = (const char*)d_Wp + (size_t)wid * 1024 + (size_t)lane * 8;
        auto loadB = [&](int gt, uint2* q) {
            const char* src = wpB + (size_t)gt * 8192;
            q[0] = *reinterpret_cast<const uint2*>(src);          // s0,b0
            q[1] = *reinterpret_cast<const uint2*>(src + 256);    // s0,b1
            q[2] = *reinterpret_cast<const uint2*>(src + 512);    // s1,b0
            q[3] = *reinterpret_cast<const uint2*>(src + 768);    // s1,b1
        };

        const int gt0   = headT0 + pos0 * 4;
        const int gtEnd = gt0 + npos * 4;

        do_im2col(0, 0);
        uint2 bq[4];
        loadB(gt0, bq);
        __syncthreads();          // A(0) visible

        int gt = gt0;
        for (int gp = 0; gp < npos; ++gp) {
            const int buf = gp & 1;
            const uint32_t aG = sbase + SM_A + buf * ABUF;

            #pragma unroll 4
            for (int st = 0; st < 4; ++st, ++gt) {
                uint2 bqn[4];
                if (gt + 1 < gtEnd) loadB(gt + 1, bqn);

                const uint32_t aB = aG + st * ASUB;
                #pragma unroll
                for (int s = 0; s < 2; s++) {
                    uint32_t af[4][4];
                    #pragma unroll
                    for (int mf = 0; mf < 4; mf++)
                        ldsm4(af[mf], aB + mf * 1280 + s * 32 + laneOff);
                    const uint32_t* q0 = reinterpret_cast<const uint32_t*>(&bq[s * 2]);
                    const uint32_t* q1 = reinterpret_cast<const uint32_t*>(&bq[s * 2 + 1]);
                    // single fp16 pass: 8 HMMAs, no prmt
                    #pragma unroll
                    for (int mf = 0; mf < 4; mf++)
                        hmma16(acc[mf][0], af[mf], q0[0], q1[0]);
                    #pragma unroll
                    for (int mf = 0; mf < 4; mf++)
                        hmma16(acc[mf][1], af[mf], q0[1], q1[1]);
                }
                if (gt + 1 < gtEnd) {
                    bq[0] = bqn[0]; bq[1] = bqn[1];
                    bq[2] = bqn[2]; bq[3] = bqn[3];
                }
            }

            if (gp + 1 < npos) {
                do_im2col(gp + 1, buf ^ 1);
                __syncthreads();      // A(gp+1) visible to all warps
            }
        }

        // epilogue: write partial sums to slab
        {
            float* slabp = d_Hpart + (size_t)slab * (NBOX * HID) + (size_t)box0 * HID;
            const int rb = lane >> 2;
            const int cb = wid * 16 + (lane & 3) * 2;
            #pragma unroll
            for (int mf = 0; mf < 4; mf++) {
                #pragma unroll
                for (int nf = 0; nf < 2; nf++) {
                    int rr = rb + mf * 16;
                    int cc = cb + nf * 8;
                    *reinterpret_cast<float2*>(&slabp[rr * HID + cc]) =
                        make_float2(acc[mf][nf][0], acc[mf][nf][1]);
                    *reinterpret_cast<float2*>(&slabp[(rr + 8) * HID + cc]) =
                        make_float2(acc[mf][nf][2], acc[mf][nf][3]);
                }
            }
        }
        __syncthreads();   // boxp/s_item/bufs safe for next item
    }
}

// ---------------- finisher: slabs -> H -> layer-2; global head inline ----------------
__global__ void __launch_bounds__(256, 2)
finisher_kernel(const float* __restrict__ b1a, const float* __restrict__ W2a,
                const float* __restrict__ b2a,
                const float* __restrict__ b1b, const float* __restrict__ W2b,
                const float* __restrict__ b2b,
                const float* __restrict__ b1c, const float* __restrict__ W2c,
                const float* __restrict__ b2c,
                const float* __restrict__ scale_w,
                const float* __restrict__ Wg, const float* __restrict__ bg,
                float* __restrict__ out) {
    __shared__ float Hs[8192];
    __shared__ float sG[16];
    const int tid  = threadIdx.x;
    const int box0 = blockIdx.x * 64;

    if (tid < 16) {
        float s = bg[tid];
        #pragma unroll 8
        for (int c = 0; c < CC; c++) s += d_gf[c] * Wg[tid * CC + c];
        sG[tid] = s;
    }
    __syncthreads();
    for (int idx = tid; idx < 1024; idx += 256) {
        int mm = idx >> 4;
        int j  = idx & 15;
        out[(size_t)(box0 + mm) * 64 + 48 + j] = sG[j];
    }

    #pragma unroll
    for (int h = 0; h < 3; h++) {
        const float *b1, *W2, *b2;
        int slab0, nslab, od, col0, swi;
        if (h == 0)      { b1 = b1a; W2 = W2a; b2 = b2a; slab0 = 6; nslab = 1; od = 22; col0 = 0;  swi = 0; }
        else if (h == 1) { b1 = b1b; W2 = W2b; b2 = b2b; slab0 = 4; nslab = 2; od = 21; col0 = 22; swi = 1; }
        else             { b1 = b1c; W2 = W2c; b2 = b2c; slab0 = 0; nslab = 4; od = 5;  col0 = 43; swi = 2; }

        const size_t gbase = (size_t)box0 * HID;
        for (int i = tid * 4; i < 8192; i += 1024) {
            float4 s = *reinterpret_cast<const float4*>(
                &d_Hpart[(size_t)slab0 * (NBOX * HID) + gbase + i]);
            for (int q = 1; q < nslab; q++) {
                float4 t = *reinterpret_cast<const float4*>(
                    &d_Hpart[(size_t)(slab0 + q) * (NBOX * HID) + gbase + i]);
                s.x += t.x; s.y += t.y; s.z += t.z; s.w += t.w;
            }
            int n = i & 127;
            float4 bb = *reinterpret_cast<const float4*>(&b1[n]);
            s.x = fmaxf(s.x + bb.x, 0.0f);
            s.y = fmaxf(s.y + bb.y, 0.0f);
            s.z = fmaxf(s.z + bb.z, 0.0f);
            s.w = fmaxf(s.w + bb.w, 0.0f);
            *reinterpret_cast<float4*>(&Hs[i]) = s;
        }
        __syncthreads();

        const float sw = __ldg(&scale_w[swi]);
        const int njobs = od << 6;
        for (int job = tid; job < njobs; job += 256) {
            int mm = job / od;
            int o  = job - mm * od;
            float s = __ldg(&b2[o]);
            const float4* hrow = reinterpret_cast<const float4*>(&Hs[mm * 128]);
            const float4* wrow = reinterpret_cast<const float4*>(&W2[o * 128]);
            #pragma unroll 8
            for (int qq = 0; qq < 32; qq++) {
                float4 h4 = hrow[qq];
                float4 w4 = __ldg(&wrow[qq]);
                s += h4.x * w4.x + h4.y * w4.y + h4.z * w4.z + h4.w * w4.w;
            }
            out[(size_t)(box0 + mm) * 64 + col0 + o] = fmaxf(s, 0.0f) * sw;
        }
        __syncthreads();
    }
}

// ---------------- launch ----------------
extern "C" void kernel_launch(void* const* d_in, const int* in_sizes, int n_in,
                              void* d_out, int out_size) {
    const float* fm      = (const float*)d_in[0];
    const float* boxes   = (const float*)d_in[1];
    const float* W1a     = (const float*)d_in[2];
    const float* b1a     = (const float*)d_in[3];
    const float* W2a     = (const float*)d_in[4];
    const float* b2a     = (const float*)d_in[5];
    const float* W1b     = (const float*)d_in[6];
    const float* b1b     = (const float*)d_in[7];
    const float* W2b     = (const float*)d_in[8];
    const float* b2b     = (const float*)d_in[9];
    const float* W1c     = (const float*)d_in[10];
    const float* b1c     = (const float*)d_in[11];
    const float* W2c     = (const float*)d_in[12];
    const float* b2c     = (const float*)d_in[13];
    const float* scale_w = (const float*)d_in[14];
    const float* Wg      = (const float*)d_in[15];
    const float* bg      = (const float*)d_in[16];
    float* out = (float*)d_out;

    cudaFuncSetAttribute(layer1_kernel,
                         cudaFuncAttributeMaxDynamicSharedMemorySize, SM_TOT);

    prep_all_kernel<<<PREP_BLKS, 256>>>(fm, W1a, W1b, W1c);

    layer1_kernel<<<296, 256, SM_TOT>>>(boxes);

    finisher_kernel<<<NBOX / 64, 256>>>(b1a, W2a, b2a,
                                        b1b, W2b, b2b,
                                        b1c, W2c, b2c,
                                        scale_w, Wg, bg, out);
}

// round 16
// speedup vs baseline: 1.5533x; 1.2474x over previous
#include <cuda_runtime.h>
#include <cuda_fp16.h>
#include <cstdint>

// ---------------- problem constants ----------------
#define CC      64
#define HH      120
#define WW      120
#define NBOX    8192
#define HID     128
#define SCOORD  (119.0f / 960.0f)

#define FIN_A   576
#define FIN_B   3136
#define FIN_C   7744

// k16-tiles per head: A 36, B 196, C 484 -> 716; group = 1 position = 4 tiles
#define T_A0    0
#define T_B0    36
#define T_C0    232
#define NTILES  716
#define N_ITEMS 896         // c: 4 chunks x 128 box-tiles, b: 2 x 128, a: 1 x 128
#define NSLAB   7           // c: 0-3, b: 4-5, a: 6

// smem layout (dynamic): boxp 1024 | A bufs 2 x 12480
// A sub-tile: 64 rows x 32B fp16 data, 48B stride (16B pad, ldsm-conflict-free)
#define ASUB    3120        // 64*48 + 48 pad
#define ABUF    12480       // 4 sub-tiles (one position)
#define SM_A    1024
#define SM_TOT  (SM_A + 2 * ABUF)      // 25984

// merged prep grid split
#define PREP_FM_BLKS  3600              // 921600 / 256
#define PREP_WP_BLKS  2864              // NTILES*1024 / 256
#define PREP_GF_BLKS  64
#define PREP_BLKS     (PREP_FM_BLKS + PREP_WP_BLKS + PREP_GF_BLKS)

// ---------------- device scratch ----------------
__device__ float    d_fmT[HH * WW * CC];            // [y][x][c]
__device__ uint32_t d_Wp[NTILES * 1024];            // fragment-linear fp16 B (k-pairs)
__device__ float    d_Hpart[NSLAB * NBOX * HID];    // partial H slabs
__device__ float    d_gf[CC];
__device__ int      d_ctr;

// ---------------- helpers ----------------
__device__ __forceinline__ void ldsm4(uint32_t* r, uint32_t addr) {
    asm volatile("ldmatrix.sync.aligned.m8n8.x4.shared.b16 {%0,%1,%2,%3}, [%4];"
                 : "=r"(r[0]), "=r"(r[1]), "=r"(r[2]), "=r"(r[3]) : "r"(addr));
}
__device__ __forceinline__ void hmma16(float* c, const uint32_t* a,
                                       uint32_t b0, uint32_t b1) {
    asm volatile("mma.sync.aligned.m16n8k16.row.col.f32.f16.f16.f32 "
                 "{%0,%1,%2,%3}, {%4,%5,%6,%7}, {%8,%9}, {%0,%1,%2,%3};"
                 : "+f"(c[0]), "+f"(c[1]), "+f"(c[2]), "+f"(c[3])
                 : "r"(a[0]), "r"(a[1]), "r"(a[2]), "r"(a[3]), "r"(b0), "r"(b1));
}
__device__ __forceinline__ uint32_t packf16x2(float lo, float hi) {
    // low 16 bits = f16(lo), high = f16(hi)
    __half2 h = __floats2half2_rn(lo, hi);
    return *reinterpret_cast<uint32_t*>(&h);
}
__device__ __forceinline__ uint32_t smem_u32(const void* p) {
    uint32_t a;
    asm("{ .reg .u64 t; cvta.to.shared.u64 t, %1; cvt.u32.u64 %0, t; }" : "=r"(a) : "l"(p));
    return a;
}

// ---------------- merged prep kernel ----------------
// blocks [0,3600): fm transpose; [3600,6464): B fragment images; [6464,6528): gf
__global__ void prep_all_kernel(const float* __restrict__ fm,
                                const float* __restrict__ W1a,
                                const float* __restrict__ W1b,
                                const float* __restrict__ W1c) {
    __shared__ float red[8];
    const int b = blockIdx.x;
    if (b < PREP_FM_BLKS) {
        int idx = b * 256 + threadIdx.x;
        if (idx == 0) d_ctr = 0;
        int c = idx & 63;
        int p = idx >> 6;
        d_fmT[idx] = fm[c * (HH * WW) + p];
    } else if (b < PREP_FM_BLKS + PREP_WP_BLKS) {
        int idx = (b - PREP_FM_BLKS) * 256 + threadIdx.x;
        // word (tg, wn8, b01, lane, nf2) at tg*1024 + wn8*128 + b01*64 + lane*2 + nf2
        // content: k-pair kk = b01*8 + 2*(lane&3); n = wn8*16 + nf2*8 + (lane>>2)
        int tg   = idx >> 10;
        int w    = idx & 1023;
        int nf2  = w & 1;
        int lane = (w >> 1) & 31;
        int b01  = (w >> 6) & 1;
        int wn8  = (w >> 7) & 7;
        int kk = b01 * 8 + 2 * (lane & 3);
        int n  = wn8 * 16 + nf2 * 8 + (lane >> 2);
        const float* W; int fin, r2, tr;
        if (tg < T_B0)      { W = W1a; fin = FIN_A; r2 = 9;   tr = tg; }
        else if (tg < T_C0) { W = W1b; fin = FIN_B; r2 = 49;  tr = tg - T_B0; }
        else                { W = W1c; fin = FIN_C; r2 = 121; tr = tg - T_C0; }
        int kr0 = tr * 16 + kk;
        int p0  = kr0 >> 6, c0 = kr0 & 63;
        int kr1 = kr0 + 1;
        int p1  = kr1 >> 6, c1 = kr1 & 63;
        d_Wp[idx] = packf16x2(W[n * fin + c0 * r2 + p0], W[n * fin + c1 * r2 + p1]);
    } else {
        int c = b - (PREP_FM_BLKS + PREP_WP_BLKS);
        float s = 0.0f;
        for (int i = threadIdx.x; i < HH * WW; i += 256) s += fm[c * (HH * WW) + i];
        #pragma unroll
        for (int off = 16; off; off >>= 1) s += __shfl_down_sync(0xffffffffu, s, off);
        if ((threadIdx.x & 31) == 0) red[threadIdx.x >> 5] = s;
        __syncthreads();
        if (threadIdx.x < 8) {
            s = red[threadIdx.x];
            #pragma unroll
            for (int off = 4; off; off >>= 1) s += __shfl_down_sync(0xffu, s, off);
            if (threadIdx.x == 0) d_gf[c] = s / (float)(HH * WW);
        }
    }
}

// ---------------- persistent HMMA layer-1 kernel ----------------
// CTA tile 64 boxes x 128 hidden, 256 threads = 8 warps all in n (warp tile 64x16).
// 2 CTAs/SM. Plain fp16 A and B (no split): 8 HMMAs + 4 ldsm4 per k16-tile/warp.

__global__ void __launch_bounds__(256, 2)
layer1_kernel(const float* __restrict__ boxes) {
    extern __shared__ char smem[];
    float* boxp = (float*)smem;
    const uint32_t sbase = smem_u32(smem);
    __shared__ int s_item;

    const int tid    = threadIdx.x;
    const int wid    = tid >> 5;       // 0..7 = n-sixteenth
    const int lane   = tid & 31;
    const uint32_t laneOff = (uint32_t)(((lane & 7) + ((lane >> 3) & 1) * 8) * 48
                                        + (lane >> 4) * 16);
    const int f4i    = lane & 15;      // im2col: float4 channel index
    const int boxSel = lane >> 4;      // im2col: which of the pass's 2 boxes

    while (true) {
        if (tid == 0) s_item = atomicAdd(&d_ctr, 1);
        __syncthreads();
        const int item = s_item;
        if (item >= N_ITEMS) break;

        // decode item -> (head, 64-box tile, position chunk)
        int bt, pos0, npos, slab, r, headT0;
        float invr;
        if (item < 512) {                 // head c: 4 chunks {31,30,30,30}
            int ci = item >> 7; bt = item & 127;
            const int cst[4] = {0, 31, 61, 91};
            pos0 = cst[ci]; npos = (ci == 0) ? 31 : 30; slab = ci;
            r = 11; invr = 0.1f; headT0 = T_C0;
        } else if (item < 768) {          // head b: 2 chunks {25,24}
            int rel = item - 512;
            int ci = rel >> 7; bt = rel & 127;
            pos0 = ci ? 25 : 0; npos = ci ? 24 : 25; slab = 4 + ci;
            r = 7; invr = 1.0f / 6.0f; headT0 = T_B0;
        } else {                          // head a: 9 positions
            bt = item - 768;
            pos0 = 0; npos = 9; slab = 6;
            r = 3; invr = 0.5f; headT0 = T_A0;
        }
        const int box0 = bt * 64;

        if (tid < 64) {
            float4 b4 = __ldg(reinterpret_cast<const float4*>(boxes) + (box0 + tid));
            float4 o;
            o.x = b4.x * SCOORD;
            o.y = (b4.z - b4.x) * SCOORD;
            o.z = b4.y * SCOORD;
            o.w = (b4.w - b4.y) * SCOORD;
            *reinterpret_cast<float4*>(&boxp[tid * 4]) = o;
        }
        __syncthreads();

        float acc[4][2][4];               // [mf][nf2][quad]
        #pragma unroll
        for (int i = 0; i < 4; i++)
            #pragma unroll
            for (int j = 0; j < 2; j++)
                #pragma unroll
                for (int q = 0; q < 4; q++) acc[i][j][q] = 0.0f;

        // ---- coalesced im2col: one position group (64 boxes, 4 passes) ----
        // thread -> (4 channels, 1 box); stores one uint2 (4 fp16) per pass
        auto do_im2col = [&](int gp, int buf) {
            const int pos = pos0 + gp;
            const int py  = pos / r;
            const int px  = pos - py * r;
            const float tx = px * invr;
            const float ty = py * invr;
            char* aB = smem + SM_A + buf * ABUF + (f4i >> 2) * ASUB + (f4i & 3) * 8;
            const float4* f = reinterpret_cast<const float4*>(d_fmT);
            #pragma unroll
            for (int p = 0; p < 4; ++p) {
                const int mb = p * 16 + (wid << 1) + boxSel;
                float4 bpv = *reinterpret_cast<const float4*>(&boxp[mb * 4]);
                float ix = fmaf(bpv.y, tx, bpv.x);
                float iy = fmaf(bpv.w, ty, bpv.z);
                float x0f = floorf(ix), y0f = floorf(iy);
                float wx = ix - x0f, wy = iy - y0f;
                int x0 = (int)x0f, y0 = (int)y0f;
                int x1 = x0 + 1,   y1 = y0 + 1;
                float vx0 = (x0 >= 0 && x0 < WW) ? 1.0f : 0.0f;
                float vx1 = (x1 >= 0 && x1 < WW) ? 1.0f : 0.0f;
                float vy0 = (y0 >= 0 && y0 < HH) ? 1.0f : 0.0f;
                float vy1 = (y1 >= 0 && y1 < HH) ? 1.0f : 0.0f;
                float w00 = (1.0f - wx) * (1.0f - wy) * vx0 * vy0;
                float w01 = wx * (1.0f - wy) * vx1 * vy0;
                float w10 = (1.0f - wx) * wy * vx0 * vy1;
                float w11 = wx * wy * vx1 * vy1;
                int cx0 = min(max(x0, 0), WW - 1), cx1 = min(max(x1, 0), WW - 1);
                int cy0 = min(max(y0, 0), HH - 1), cy1 = min(max(y1, 0), HH - 1);
                float4 t00 = __ldg(&f[(cy0 * WW + cx0) * 16 + f4i]);
                float4 t01 = __ldg(&f[(cy0 * WW + cx1) * 16 + f4i]);
                float4 t10 = __ldg(&f[(cy1 * WW + cx0) * 16 + f4i]);
                float4 t11 = __ldg(&f[(cy1 * WW + cx1) * 16 + f4i]);
                float4 v;
                v.x = w00 * t00.x + w01 * t01.x + w10 * t10.x + w11 * t11.x;
                v.y = w00 * t00.y + w01 * t01.y + w10 * t10.y + w11 * t11.y;
                v.z = w00 * t00.z + w01 * t01.z + w10 * t10.z + w11 * t11.z;
                v.w = w00 * t00.w + w01 * t01.w + w10 * t10.w + w11 * t11.w;
                uint2 wv;
                wv.x = packf16x2(v.x, v.y);
                wv.y = packf16x2(v.z, v.w);
                *reinterpret_cast<uint2*>(aB + mb * 48) = wv;
            }
        };

        // B fragments: 2 x uint2 per tile (b01=0/1), n16 slice for this warp
        // byte layout: tile 4096, wn8 512, b01 256, lane 8, nf2 4
        const char* wpB = (const char*)d_Wp + (size_t)wid * 512 + (size_t)lane * 8;
        auto loadB = [&](int gt, uint2* q) {
            const char* src = wpB + (size_t)gt * 4096;
            q[0] = *reinterpret_cast<const uint2*>(src);          // b01=0 (k0-7)
            q[1] = *reinterpret_cast<const uint2*>(src + 256);    // b01=1 (k8-15)
        };

        const int gt0   = headT0 + pos0 * 4;
        const int gtEnd = gt0 + npos * 4;

        do_im2col(0, 0);
        uint2 bq[2];
        loadB(gt0, bq);
        __syncthreads();          // A(0) visible

        int gt = gt0;
        for (int gp = 0; gp < npos; ++gp) {
            const int buf = gp & 1;
            const uint32_t aG = sbase + SM_A + buf * ABUF;

            #pragma unroll 4
            for (int st = 0; st < 4; ++st, ++gt) {
                uint2 bqn[2];
                if (gt + 1 < gtEnd) loadB(gt + 1, bqn);

                const uint32_t aB = aG + st * ASUB;
                uint32_t af[4][4];
                #pragma unroll
                for (int mf = 0; mf < 4; mf++)
                    ldsm4(af[mf], aB + mf * 768 + laneOff);

                // 8 HMMAs per tile: nf2 x mf
                #pragma unroll
                for (int mf = 0; mf < 4; mf++)
                    hmma16(acc[mf][0], af[mf], bq[0].x, bq[1].x);
                #pragma unroll
                for (int mf = 0; mf < 4; mf++)
                    hmma16(acc[mf][1], af[mf], bq[0].y, bq[1].y);

                if (gt + 1 < gtEnd) { bq[0] = bqn[0]; bq[1] = bqn[1]; }
            }

            if (gp + 1 < npos) {
                do_im2col(gp + 1, buf ^ 1);
                __syncthreads();      // A(gp+1) visible to all warps
            }
        }

        // epilogue: write partial sums to slab
        {
            float* slabp = d_Hpart + (size_t)slab * (NBOX * HID) + (size_t)box0 * HID;
            const int rb = lane >> 2;
            const int cb = wid * 16 + (lane & 3) * 2;
            #pragma unroll
            for (int mf = 0; mf < 4; mf++) {
                #pragma unroll
                for (int nf = 0; nf < 2; nf++) {
                    int rr = rb + mf * 16;
                    int cc = cb + nf * 8;
                    *reinterpret_cast<float2*>(&slabp[rr * HID + cc]) =
                        make_float2(acc[mf][nf][0], acc[mf][nf][1]);
                    *reinterpret_cast<float2*>(&slabp[(rr + 8) * HID + cc]) =
                        make_float2(acc[mf][nf][2], acc[mf][nf][3]);
                }
            }
        }
        __syncthreads();   // boxp/s_item/bufs safe for next item
    }
}

// ---------------- finisher: slabs -> H -> layer-2; global head inline ----------------
__global__ void __launch_bounds__(256, 2)
finisher_kernel(const float* __restrict__ b1a, const float* __restrict__ W2a,
                const float* __restrict__ b2a,
                const float* __restrict__ b1b, const float* __restrict__ W2b,
                const float* __restrict__ b2b,
                const float* __restrict__ b1c, const float* __restrict__ W2c,
                const float* __restrict__ b2c,
                const float* __restrict__ scale_w,
                const float* __restrict__ Wg, const float* __restrict__ bg,
                float* __restrict__ out) {
    __shared__ float Hs[8192];
    __shared__ float sG[16];
    const int tid  = threadIdx.x;
    const int box0 = blockIdx.x * 64;

    if (tid < 16) {
        float s = bg[tid];
        #pragma unroll 8
        for (int c = 0; c < CC; c++) s += d_gf[c] * Wg[tid * CC + c];
        sG[tid] = s;
    }
    __syncthreads();
    for (int idx = tid; idx < 1024; idx += 256) {
        int mm = idx >> 4;
        int j  = idx & 15;
        out[(size_t)(box0 + mm) * 64 + 48 + j] = sG[j];
    }

    #pragma unroll
    for (int h = 0; h < 3; h++) {
        const float *b1, *W2, *b2;
        int slab0, nslab, od, col0, swi;
        if (h == 0)      { b1 = b1a; W2 = W2a; b2 = b2a; slab0 = 6; nslab = 1; od = 22; col0 = 0;  swi = 0; }
        else if (h == 1) { b1 = b1b; W2 = W2b; b2 = b2b; slab0 = 4; nslab = 2; od = 21; col0 = 22; swi = 1; }
        else             { b1 = b1c; W2 = W2c; b2 = b2c; slab0 = 0; nslab = 4; od = 5;  col0 = 43; swi = 2; }

        const size_t gbase = (size_t)box0 * HID;
        for (int i = tid * 4; i < 8192; i += 1024) {
            float4 s = *reinterpret_cast<const float4*>(
                &d_Hpart[(size_t)slab0 * (NBOX * HID) + gbase + i]);
            for (int q = 1; q < nslab; q++) {
                float4 t = *reinterpret_cast<const float4*>(
                    &d_Hpart[(size_t)(slab0 + q) * (NBOX * HID) + gbase + i]);
                s.x += t.x; s.y += t.y; s.z += t.z; s.w += t.w;
            }
            int n = i & 127;
            float4 bb = *reinterpret_cast<const float4*>(&b1[n]);
            s.x = fmaxf(s.x + bb.x, 0.0f);
            s.y = fmaxf(s.y + bb.y, 0.0f);
            s.z = fmaxf(s.z + bb.z, 0.0f);
            s.w = fmaxf(s.w + bb.w, 0.0f);
            *reinterpret_cast<float4*>(&Hs[i]) = s;
        }
        __syncthreads();

        const float sw = __ldg(&scale_w[swi]);
        const int njobs = od << 6;
        for (int job = tid; job < njobs; job += 256) {
            int mm = job / od;
            int o  = job - mm * od;
            float s = __ldg(&b2[o]);
            const float4* hrow = reinterpret_cast<const float4*>(&Hs[mm * 128]);
            const float4* wrow = reinterpret_cast<const float4*>(&W2[o * 128]);
            #pragma unroll 8
            for (int qq = 0; qq < 32; qq++) {
                float4 h4 = hrow[qq];
                float4 w4 = __ldg(&wrow[qq]);
                s += h4.x * w4.x + h4.y * w4.y + h4.z * w4.z + h4.w * w4.w;
            }
            out[(size_t)(box0 + mm) * 64 + col0 + o] = fmaxf(s, 0.0f) * sw;
        }
        __syncthreads();
    }
}

// ---------------- launch ----------------
extern "C" void kernel_launch(void* const* d_in, const int* in_sizes, int n_in,
                              void* d_out, int out_size) {
    const float* fm      = (const float*)d_in[0];
    const float* boxes   = (const float*)d_in[1];
    const float* W1a     = (const float*)d_in[2];
    const float* b1a     = (const float*)d_in[3];
    const float* W2a     = (const float*)d_in[4];
    const float* b2a     = (const float*)d_in[5];
    const float* W1b     = (const float*)d_in[6];
    const float* b1b     = (const float*)d_in[7];
    const float* W2b     = (const float*)d_in[8];
    const float* b2b     = (const float*)d_in[9];
    const float* W1c     = (const float*)d_in[10];
    const float* b1c     = (const float*)d_in[11];
    const float* W2c     = (const float*)d_in[12];
    const float* b2c     = (const float*)d_in[13];
    const float* scale_w = (const float*)d_in[14];
    const float* Wg      = (const float*)d_in[15];
    const float* bg      = (const float*)d_in[16];
    float* out = (float*)d_out;

    cudaFuncSetAttribute(layer1_kernel,
                         cudaFuncAttributeMaxDynamicSharedMemorySize, SM_TOT);

    prep_all_kernel<<<PREP_BLKS, 256>>>(fm, W1a, W1b, W1c);

    layer1_kernel<<<296, 256, SM_TOT>>>(boxes);

    finisher_kernel<<<NBOX / 64, 256>>>(b1a, W2a, b2a,
                                        b1b, W2b, b2b,
                                        b1c, W2c, b2c,
                                        scale_w, Wg, bg, out);
}

// round 17
// speedup vs baseline: 1.6861x; 1.0855x over previous
#include <cuda_runtime.h>
#include <cuda_fp16.h>
#include <cstdint>

// ---------------- problem constants ----------------
#define CC      64
#define HH      120
#define WW      120
#define NBOX    8192
#define HID     128
#define SCOORD  (119.0f / 960.0f)

#define FIN_A   576
#define FIN_B   3136
#define FIN_C   7744

// k16-tiles per head: A 36, B 196, C 484 -> 716; group = 1 position = 4 tiles
#define T_A0    0
#define T_B0    36
#define T_C0    232
#define NTILES  716
#define N_ITEMS 896         // c: 4 chunks x 128 box-tiles, b: 2 x 128, a: 1 x 128
#define NSLAB   7           // c: 0-3, b: 4-5, a: 6

// smem layout (dynamic): boxp 1024 | A bufs 2 x 12480
#define ASUB    3120        // 64 rows x 48B stride + 48 pad
#define ABUF    12480       // 4 sub-tiles (one position)
#define SM_A    1024
#define SM_TOT  (SM_A + 2 * ABUF)      // 25984

// merged prep grid split
#define PREP_FM_BLKS  3600              // 921600 / 256
#define PREP_WP_BLKS  2864              // NTILES*1024 / 256
#define PREP_GF_BLKS  64
#define PREP_BLKS     (PREP_FM_BLKS + PREP_WP_BLKS + PREP_GF_BLKS)

// ---------------- device scratch ----------------
__device__ __half   d_fmT[HH * WW * CC];            // [y][x][c] fp16
__device__ uint32_t d_Wp[NTILES * 1024];            // fragment-linear fp16 B (k-pairs)
__device__ float    d_Hpart[NSLAB * NBOX * HID];    // partial H slabs
__device__ float    d_gf[CC];
__device__ int      d_ctr;

// ---------------- helpers ----------------
__device__ __forceinline__ void ldsm4(uint32_t* r, uint32_t addr) {
    asm volatile("ldmatrix.sync.aligned.m8n8.x4.shared.b16 {%0,%1,%2,%3}, [%4];"
                 : "=r"(r[0]), "=r"(r[1]), "=r"(r[2]), "=r"(r[3]) : "r"(addr));
}
__device__ __forceinline__ void hmma16(float* c, const uint32_t* a,
                                       uint32_t b0, uint32_t b1) {
    asm volatile("mma.sync.aligned.m16n8k16.row.col.f32.f16.f16.f32 "
                 "{%0,%1,%2,%3}, {%4,%5,%6,%7}, {%8,%9}, {%0,%1,%2,%3};"
                 : "+f"(c[0]), "+f"(c[1]), "+f"(c[2]), "+f"(c[3])
                 : "r"(a[0]), "r"(a[1]), "r"(a[2]), "r"(a[3]), "r"(b0), "r"(b1));
}
__device__ __forceinline__ uint32_t packf16x2(float lo, float hi) {
    __half2 h = __floats2half2_rn(lo, hi);
    return *reinterpret_cast<uint32_t*>(&h);
}
__device__ __forceinline__ uint32_t smem_u32(const void* p) {
    uint32_t a;
    asm("{ .reg .u64 t; cvta.to.shared.u64 t, %1; cvt.u32.u64 %0, t; }" : "=r"(a) : "l"(p));
    return a;
}

// ---------------- merged prep kernel ----------------
__global__ void prep_all_kernel(const float* __restrict__ fm,
                                const float* __restrict__ W1a,
                                const float* __restrict__ W1b,
                                const float* __restrict__ W1c) {
    __shared__ float red[8];
    const int b = blockIdx.x;
    if (b < PREP_FM_BLKS) {
        int idx = b * 256 + threadIdx.x;
        if (idx == 0) d_ctr = 0;
        int c = idx & 63;
        int p = idx >> 6;
        d_fmT[idx] = __float2half(fm[c * (HH * WW) + p]);
    } else if (b < PREP_FM_BLKS + PREP_WP_BLKS) {
        int idx = (b - PREP_FM_BLKS) * 256 + threadIdx.x;
        int tg   = idx >> 10;
        int w    = idx & 1023;
        int nf2  = w & 1;
        int lane = (w >> 1) & 31;
        int b01  = (w >> 6) & 1;
        int wn8  = (w >> 7) & 7;
        int kk = b01 * 8 + 2 * (lane & 3);
        int n  = wn8 * 16 + nf2 * 8 + (lane >> 2);
        const float* W; int fin, r2, tr;
        if (tg < T_B0)      { W = W1a; fin = FIN_A; r2 = 9;   tr = tg; }
        else if (tg < T_C0) { W = W1b; fin = FIN_B; r2 = 49;  tr = tg - T_B0; }
        else                { W = W1c; fin = FIN_C; r2 = 121; tr = tg - T_C0; }
        int kr0 = tr * 16 + kk;
        int p0  = kr0 >> 6, c0 = kr0 & 63;
        int kr1 = kr0 + 1;
        int p1  = kr1 >> 6, c1 = kr1 & 63;
        d_Wp[idx] = packf16x2(W[n * fin + c0 * r2 + p0], W[n * fin + c1 * r2 + p1]);
    } else {
        int c = b - (PREP_FM_BLKS + PREP_WP_BLKS);
        float s = 0.0f;
        for (int i = threadIdx.x; i < HH * WW; i += 256) s += fm[c * (HH * WW) + i];
        #pragma unroll
        for (int off = 16; off; off >>= 1) s += __shfl_down_sync(0xffffffffu, s, off);
        if ((threadIdx.x & 31) == 0) red[threadIdx.x >> 5] = s;
        __syncthreads();
        if (threadIdx.x < 8) {
            s = red[threadIdx.x];
            #pragma unroll
            for (int off = 4; off; off >>= 1) s += __shfl_down_sync(0xffu, s, off);
            if (threadIdx.x == 0) d_gf[c] = s / (float)(HH * WW);
        }
    }
}

// ---------------- persistent HMMA layer-1 kernel ----------------
// CTA tile 64 boxes x 128 hidden, 256 threads = 8 warps all in n (warp tile 64x16).
// 2 CTAs/SM. Plain fp16 A/B; im2col: no masks/clamps (coords provably in-range),
// fp16 taps (uint2 loads) + HFMA2 combine.

__global__ void __launch_bounds__(256, 2)
layer1_kernel(const float* __restrict__ boxes) {
    extern __shared__ char smem[];
    float* boxp = (float*)smem;
    const uint32_t sbase = smem_u32(smem);
    __shared__ int s_item;

    const int tid    = threadIdx.x;
    const int wid    = tid >> 5;       // 0..7 = n-sixteenth
    const int lane   = tid & 31;
    const uint32_t laneOff = (uint32_t)(((lane & 7) + ((lane >> 3) & 1) * 8) * 48
                                        + (lane >> 4) * 16);
    const int f4i    = lane & 15;      // im2col: 4-channel group index
    const int boxSel = lane >> 4;      // im2col: which of the pass's 2 boxes

    while (true) {
        if (tid == 0) s_item = atomicAdd(&d_ctr, 1);
        __syncthreads();
        const int item = s_item;
        if (item >= N_ITEMS) break;

        int bt, pos0, npos, slab, r, headT0;
        float invr;
        if (item < 512) {                 // head c: 4 chunks {31,30,30,30}
            int ci = item >> 7; bt = item & 127;
            const int cst[4] = {0, 31, 61, 91};
            pos0 = cst[ci]; npos = (ci == 0) ? 31 : 30; slab = ci;
            r = 11; invr = 0.1f; headT0 = T_C0;
        } else if (item < 768) {          // head b: 2 chunks {25,24}
            int rel = item - 512;
            int ci = rel >> 7; bt = rel & 127;
            pos0 = ci ? 25 : 0; npos = ci ? 24 : 25; slab = 4 + ci;
            r = 7; invr = 1.0f / 6.0f; headT0 = T_B0;
        } else {                          // head a: 9 positions
            bt = item - 768;
            pos0 = 0; npos = 9; slab = 6;
            r = 3; invr = 0.5f; headT0 = T_A0;
        }
        const int box0 = bt * 64;

        if (tid < 64) {
            float4 b4 = __ldg(reinterpret_cast<const float4*>(boxes) + (box0 + tid));
            float4 o;
            o.x = b4.x * SCOORD;
            o.y = (b4.z - b4.x) * SCOORD;
            o.z = b4.y * SCOORD;
            o.w = (b4.w - b4.y) * SCOORD;
            *reinterpret_cast<float4*>(&boxp[tid * 4]) = o;
        }
        __syncthreads();

        float acc[4][2][4];               // [mf][nf2][quad]
        #pragma unroll
        for (int i = 0; i < 4; i++)
            #pragma unroll
            for (int j = 0; j < 2; j++)
                #pragma unroll
                for (int q = 0; q < 4; q++) acc[i][j][q] = 0.0f;

        // ---- im2col: fp16 taps, HFMA2 combine, no bounds logic ----
        auto do_im2col = [&](int gp, int buf) {
            const int pos = pos0 + gp;
            const int py  = pos / r;
            const int px  = pos - py * r;
            const float tx = px * invr;
            const float ty = py * invr;
            char* aB = smem + SM_A + buf * ABUF + (f4i >> 2) * ASUB + (f4i & 3) * 8;
            const uint2* f = reinterpret_cast<const uint2*>(d_fmT);
            #pragma unroll
            for (int p = 0; p < 4; ++p) {
                const int mb = p * 16 + (wid << 1) + boxSel;
                float4 bpv = *reinterpret_cast<const float4*>(&boxp[mb * 4]);
                float ix = fmaf(bpv.y, tx, bpv.x);      // in [0, 118.97]
                float iy = fmaf(bpv.w, ty, bpv.z);
                float x0f = floorf(ix), y0f = floorf(iy);
                float wx = ix - x0f, wy = iy - y0f;
                int x0 = (int)x0f, y0 = (int)y0f;
                float w00 = (1.0f - wx) * (1.0f - wy);
                float w01 = wx * (1.0f - wy);
                float w10 = (1.0f - wx) * wy;
                float w11 = wx * wy;
                const int o00 = (y0 * WW + x0) * 16 + f4i;
                uint2 u00 = __ldg(&f[o00]);
                uint2 u01 = __ldg(&f[o00 + 16]);          // x+1
                uint2 u10 = __ldg(&f[o00 + WW * 16]);     // y+1
                uint2 u11 = __ldg(&f[o00 + WW * 16 + 16]);
                __half2 w00h = __float2half2_rn(w00);
                __half2 w01h = __float2half2_rn(w01);
                __half2 w10h = __float2half2_rn(w10);
                __half2 w11h = __float2half2_rn(w11);
                __half2 va = __hmul2(w00h, *reinterpret_cast<__half2*>(&u00.x));
                va = __hfma2(w01h, *reinterpret_cast<__half2*>(&u01.x), va);
                va = __hfma2(w10h, *reinterpret_cast<__half2*>(&u10.x), va);
                va = __hfma2(w11h, *reinterpret_cast<__half2*>(&u11.x), va);
                __half2 vb = __hmul2(w00h, *reinterpret_cast<__half2*>(&u00.y));
                vb = __hfma2(w01h, *reinterpret_cast<__half2*>(&u01.y), vb);
                vb = __hfma2(w10h, *reinterpret_cast<__half2*>(&u10.y), vb);
                vb = __hfma2(w11h, *reinterpret_cast<__half2*>(&u11.y), vb);
                uint2 wv;
                wv.x = *reinterpret_cast<uint32_t*>(&va);
                wv.y = *reinterpret_cast<uint32_t*>(&vb);
                *reinterpret_cast<uint2*>(aB + mb * 48) = wv;
            }
        };

        // B fragments: 2 x uint2 per tile (b01=0/1), n16 slice for this warp
        const char* wpB = (const char*)d_Wp + (size_t)wid * 512 + (size_t)lane * 8;
        auto loadB = [&](int gt, uint2* q) {
            const char* src = wpB + (size_t)gt * 4096;
            q[0] = *reinterpret_cast<const uint2*>(src);
            q[1] = *reinterpret_cast<const uint2*>(src + 256);
        };

        const int gt0   = headT0 + pos0 * 4;
        const int gtEnd = gt0 + npos * 4;

        do_im2col(0, 0);
        uint2 bq[2];
        loadB(gt0, bq);
        __syncthreads();          // A(0) visible

        int gt = gt0;
        for (int gp = 0; gp < npos; ++gp) {
            const int buf = gp & 1;
            const uint32_t aG = sbase + SM_A + buf * ABUF;

            #pragma unroll 4
            for (int st = 0; st < 4; ++st, ++gt) {
                uint2 bqn[2];
                if (gt + 1 < gtEnd) loadB(gt + 1, bqn);

                const uint32_t aB = aG + st * ASUB;
                uint32_t af[4][4];
                #pragma unroll
                for (int mf = 0; mf < 4; mf++)
                    ldsm4(af[mf], aB + mf * 768 + laneOff);

                #pragma unroll
                for (int mf = 0; mf < 4; mf++)
                    hmma16(acc[mf][0], af[mf], bq[0].x, bq[1].x);
                #pragma unroll
                for (int mf = 0; mf < 4; mf++)
                    hmma16(acc[mf][1], af[mf], bq[0].y, bq[1].y);

                if (gt + 1 < gtEnd) { bq[0] = bqn[0]; bq[1] = bqn[1]; }
            }

            if (gp + 1 < npos) {
                do_im2col(gp + 1, buf ^ 1);
                __syncthreads();      // A(gp+1) visible to all warps
            }
        }

        // epilogue: write partial sums to slab
        {
            float* slabp = d_Hpart + (size_t)slab * (NBOX * HID) + (size_t)box0 * HID;
            const int rb = lane >> 2;
            const int cb = wid * 16 + (lane & 3) * 2;
            #pragma unroll
            for (int mf = 0; mf < 4; mf++) {
                #pragma unroll
                for (int nf = 0; nf < 2; nf++) {
                    int rr = rb + mf * 16;
                    int cc = cb + nf * 8;
                    *reinterpret_cast<float2*>(&slabp[rr * HID + cc]) =
                        make_float2(acc[mf][nf][0], acc[mf][nf][1]);
                    *reinterpret_cast<float2*>(&slabp[(rr + 8) * HID + cc]) =
                        make_float2(acc[mf][nf][2], acc[mf][nf][3]);
                }
            }
        }
        __syncthreads();   // boxp/s_item/bufs safe for next item
    }
}

// ---------------- finisher: slabs -> H -> layer-2; global head inline ----------------
__global__ void __launch_bounds__(256, 2)
finisher_kernel(const float* __restrict__ b1a, const float* __restrict__ W2a,
                const float* __restrict__ b2a,
                const float* __restrict__ b1b, const float* __restrict__ W2b,
                const float* __restrict__ b2b,
                const float* __restrict__ b1c, const float* __restrict__ W2c,
                const float* __restrict__ b2c,
                const float* __restrict__ scale_w,
                const float* __restrict__ Wg, const float* __restrict__ bg,
                float* __restrict__ out) {
    __shared__ float Hs[8192];
    __shared__ float sG[16];
    const int tid  = threadIdx.x;
    const int box0 = blockIdx.x * 64;

    if (tid < 16) {
        float s = bg[tid];
        #pragma unroll 8
        for (int c = 0; c < CC; c++) s += d_gf[c] * Wg[tid * CC + c];
        sG[tid] = s;
    }
    __syncthreads();
    for (int idx = tid; idx < 1024; idx += 256) {
        int mm = idx >> 4;
        int j  = idx & 15;
        out[(size_t)(box0 + mm) * 64 + 48 + j] = sG[j];
    }

    #pragma unroll
    for (int h = 0; h < 3; h++) {
        const float *b1, *W2, *b2;
        int slab0, nslab, od, col0, swi;
        if (h == 0)      { b1 = b1a; W2 = W2a; b2 = b2a; slab0 = 6; nslab = 1; od = 22; col0 = 0;  swi = 0; }
        else if (h == 1) { b1 = b1b; W2 = W2b; b2 = b2b; slab0 = 4; nslab = 2; od = 21; col0 = 22; swi = 1; }
        else             { b1 = b1c; W2 = W2c; b2 = b2c; slab0 = 0; nslab = 4; od = 5;  col0 = 43; swi = 2; }

        const size_t gbase = (size_t)box0 * HID;
        for (int i = tid * 4; i < 8192; i += 1024) {
            float4 s = *reinterpret_cast<const float4*>(
                &d_Hpart[(size_t)slab0 * (NBOX * HID) + gbase + i]);
            for (int q = 1; q < nslab; q++) {
                float4 t = *reinterpret_cast<const float4*>(
                    &d_Hpart[(size_t)(slab0 + q) * (NBOX * HID) + gbase + i]);
                s.x += t.x; s.y += t.y; s.z += t.z; s.w += t.w;
            }
            int n = i & 127;
            float4 bb = *reinterpret_cast<const float4*>(&b1[n]);
            s.x = fmaxf(s.x + bb.x, 0.0f);
            s.y = fmaxf(s.y + bb.y, 0.0f);
            s.z = fmaxf(s.z + bb.z, 0.0f);
            s.w = fmaxf(s.w + bb.w, 0.0f);
            *reinterpret_cast<float4*>(&Hs[i]) = s;
        }
        __syncthreads();

        const float sw = __ldg(&scale_w[swi]);
        const int njobs = od << 6;
        for (int job = tid; job < njobs; job += 256) {
            int mm = job / od;
            int o  = job - mm * od;
            float s = __ldg(&b2[o]);
            const float4* hrow = reinterpret_cast<const float4*>(&Hs[mm * 128]);
            const float4* wrow = reinterpret_cast<const float4*>(&W2[o * 128]);
            #pragma unroll 8
            for (int qq = 0; qq < 32; qq++) {
                float4 h4 = hrow[qq];
                float4 w4 = __ldg(&wrow[qq]);
                s += h4.x * w4.x + h4.y * w4.y + h4.z * w4.z + h4.w * w4.w;
            }
            out[(size_t)(box0 + mm) * 64 + col0 + o] = fmaxf(s, 0.0f) * sw;
        }
        __syncthreads();
    }
}

// ---------------- launch ----------------
extern "C" void kernel_launch(void* const* d_in, const int* in_sizes, int n_in,
                              void* d_out, int out_size) {
    const float* fm      = (const float*)d_in[0];
    const float* boxes   = (const float*)d_in[1];
    const float* W1a     = (const float*)d_in[2];
    const float* b1a     = (const float*)d_in[3];
    const float* W2a     = (const float*)d_in[4];
    const float* b2a     = (const float*)d_in[5];
    const float* W1b     = (const float*)d_in[6];
    const float* b1b     = (const float*)d_in[7];
    const float* W2b     = (const float*)d_in[8];
    const float* b2b     = (const float*)d_in[9];
    const float* W1c     = (const float*)d_in[10];
    const float* b1c     = (const float*)d_in[11];
    const float* W2c     = (const float*)d_in[12];
    const float* b2c     = (const float*)d_in[13];
    const float* scale_w = (const float*)d_in[14];
    const float* Wg      = (const float*)d_in[15];
    const float* bg      = (const float*)d_in[16];
    float* out = (float*)d_out;

    cudaFuncSetAttribute(layer1_kernel,
                         cudaFuncAttributeMaxDynamicSharedMemorySize, SM_TOT);

    prep_all_kernel<<<PREP_BLKS, 256>>>(fm, W1a, W1b, W1c);

    layer1_kernel<<<296, 256, SM_TOT>>>(boxes);

    finisher_kernel<<<NBOX / 64, 256>>>(b1a, W2a, b2a,
                                        b1b, W2b, b2b,
                                        b1c, W2c, b2c,
                                        scale_w, Wg, bg, out);
}